// round 15
// baseline (speedup 1.0000x reference)
#include <cuda_runtime.h>
#include <cuda_fp16.h>
#include <math.h>
#include <stdint.h>

// ---------------- problem constants ----------------
#define Dm    1024
#define Tlen  2048
#define Bb    4
#define Hh    16
#define DK    64
#define Ll    2
#define Vv    8192
#define NROW  (Bb*Tlen)          // 8192 token rows

// ---------------- scratch (device globals; no allocation allowed) ----------
__device__ float  g_x  [NROW*Dm];
__device__ float  g_h  [NROW*Dm];
__device__ __half g_h2h[NROW*Dm];
__device__ float  g_qkv[NROW*3*Dm];
__device__ __half g_yh [NROW*Dm];
__device__ __half g_hh [NROW*Dm];
__device__ float  g_ret [Ll*Hh*DK*DK];
__device__ float  g_gate[Ll*Hh*DK*DK];
__device__ __half g_wqh[Ll*3*Dm*Dm];
__device__ __half g_woh[Ll*Dm*Dm];
__device__ __half g_whh[Vv*Dm];

// ---------------- f32x2 packed math helpers ----------------
__device__ __forceinline__ unsigned long long pack2(float lo, float hi) {
    unsigned long long u;
    asm("mov.b64 %0, {%1, %2};" : "=l"(u) : "f"(lo), "f"(hi));
    return u;
}
__device__ __forceinline__ void unpack2(unsigned long long u, float& lo, float& hi) {
    asm("mov.b64 {%0, %1}, %2;" : "=f"(lo), "=f"(hi) : "l"(u));
}
#define FMA2(d, a, b, c) \
    asm("fma.rn.f32x2 %0, %1, %2, %3;" : "=l"(d) : "l"(a), "l"(b), "l"(c))
#define MUL2(d, a, b) \
    asm("mul.rn.f32x2 %0, %1, %2;" : "=l"(d) : "l"(a), "l"(b))
#define ADD2(d, a, b) \
    asm("add.rn.f32x2 %0, %1, %2;" : "=l"(d) : "l"(a), "l"(b))

// ---------------- merged fp32 -> fp16 weight conversion ----------------
#define S1 (Ll*3*Dm*Dm)
#define S2 (Ll*Dm*Dm)
#define S3 (Vv*Dm)
__global__ void __launch_bounds__(256) tohalf_all(const float* __restrict__ wq,
                                                  const float* __restrict__ wo,
                                                  const float* __restrict__ wh,
                                                  __half* __restrict__ dq,
                                                  __half* __restrict__ dol,
                                                  __half* __restrict__ dh) {
    long long i = (long long)(blockIdx.x * blockDim.x + threadIdx.x) * 4;
    const float* s; __half* d; long long off;
    if (i < S1)            { s = wq; d = dq;  off = i; }
    else if (i < S1 + S2)  { s = wo; d = dol; off = i - S1; }
    else                   { s = wh; d = dh;  off = i - S1 - S2; }
    float4 v = *(const float4*)(s + off);
    *(__half2*)(d + off)     = __floats2half2_rn(v.x, v.y);
    *(__half2*)(d + off + 2) = __floats2half2_rn(v.z, v.w);
}

// ---------------- block reduce helper (blockDim == 256) ----------------
__device__ __forceinline__ float blockReduceSum(float v, float* sh) {
    #pragma unroll
    for (int o = 16; o; o >>= 1) v += __shfl_xor_sync(0xffffffffu, v, o);
    if ((threadIdx.x & 31) == 0) sh[threadIdx.x >> 5] = v;
    __syncthreads();
    float tot = 0.f;
    #pragma unroll
    for (int i = 0; i < 8; i++) tot += sh[i];
    __syncthreads();
    return tot;
}

// ---------------- fused embedding gather + layer-0 LN ----------------
__global__ void __launch_bounds__(256) embed_ln_kernel(const int* __restrict__ ids,
                                                       const float* __restrict__ W,
                                                       const float* __restrict__ g,
                                                       const float* __restrict__ b,
                                                       float* __restrict__ x,
                                                       float* __restrict__ h) {
    __shared__ float sh[8];
    int row = blockIdx.x;
    int id  = ids[row];
    const float* xr = W + (size_t)id * Dm;
    int i0 = threadIdx.x * 4;
    float4 xv = *(const float4*)(xr + i0);
    *(float4*)(x + (size_t)row * Dm + i0) = xv;
    float s = xv.x + xv.y + xv.z + xv.w;
    float mean = blockReduceSum(s, sh) * (1.f / Dm);
    float d0 = xv.x - mean, d1 = xv.y - mean, d2 = xv.z - mean, d3 = xv.w - mean;
    float sq = d0*d0 + d1*d1 + d2*d2 + d3*d3;
    float var = blockReduceSum(sq, sh) * (1.f / Dm);
    float rstd = rsqrtf(var + 1e-5f);
    float4 gv = *(const float4*)(g + i0);
    float4 bv = *(const float4*)(b + i0);
    float4 ov;
    ov.x = d0 * rstd * gv.x + bv.x;
    ov.y = d1 * rstd * gv.y + bv.y;
    ov.z = d2 * rstd * gv.z + bv.z;
    ov.w = d3 * rstd * gv.w + bv.w;
    *(float4*)(h + (size_t)row * Dm + i0) = ov;
}

// ---------------- layernorm (fp32 out) ----------------
__global__ void __launch_bounds__(256) ln_kernel(const float* __restrict__ x,
                                                 const float* __restrict__ g,
                                                 const float* __restrict__ b,
                                                 float* __restrict__ out) {
    __shared__ float sh[8];
    int row = blockIdx.x;
    const float* xr = x + (size_t)row * Dm;
    int i0 = threadIdx.x * 4;
    float4 xv = *(const float4*)(xr + i0);
    float s = xv.x + xv.y + xv.z + xv.w;
    float mean = blockReduceSum(s, sh) * (1.f / Dm);
    float d0 = xv.x - mean, d1 = xv.y - mean, d2 = xv.z - mean, d3 = xv.w - mean;
    float sq = d0*d0 + d1*d1 + d2*d2 + d3*d3;
    float var = blockReduceSum(sq, sh) * (1.f / Dm);
    float rstd = rsqrtf(var + 1e-5f);
    float4 gv = *(const float4*)(g + i0);
    float4 bv = *(const float4*)(b + i0);
    float4 ov;
    ov.x = d0 * rstd * gv.x + bv.x;
    ov.y = d1 * rstd * gv.y + bv.y;
    ov.z = d2 * rstd * gv.z + bv.z;
    ov.w = d3 * rstd * gv.w + bv.w;
    *(float4*)(out + (size_t)row * Dm + i0) = ov;
}

// ---------------- layernorm (half out, for head GEMM A) ----------------
__global__ void __launch_bounds__(256) lnh_kernel(const float* __restrict__ x,
                                                  const float* __restrict__ g,
                                                  const float* __restrict__ b,
                                                  __half* __restrict__ out) {
    __shared__ float sh[8];
    int row = blockIdx.x;
    const float* xr = x + (size_t)row * Dm;
    int i0 = threadIdx.x * 4;
    float4 xv = *(const float4*)(xr + i0);
    float s = xv.x + xv.y + xv.z + xv.w;
    float mean = blockReduceSum(s, sh) * (1.f / Dm);
    float d0 = xv.x - mean, d1 = xv.y - mean, d2 = xv.z - mean, d3 = xv.w - mean;
    float sq = d0*d0 + d1*d1 + d2*d2 + d3*d3;
    float var = blockReduceSum(sq, sh) * (1.f / Dm);
    float rstd = rsqrtf(var + 1e-5f);
    float4 gv = *(const float4*)(g + i0);
    float4 bv = *(const float4*)(b + i0);
    *(__half2*)(out + (size_t)row * Dm + i0) =
        __floats2half2_rn(d0 * rstd * gv.x + bv.x, d1 * rstd * gv.y + bv.y);
    *(__half2*)(out + (size_t)row * Dm + i0 + 2) =
        __floats2half2_rn(d2 * rstd * gv.z + bv.z, d3 * rstd * gv.w + bv.w);
}

// ---------------- causal depthwise conv (half out) ----------------
__global__ void __launch_bounds__(256) conv_kernel(const float* __restrict__ h,
                                                   const float* __restrict__ cw,
                                                   const float* __restrict__ cb,
                                                   __half* __restrict__ out) {
    int row = blockIdx.x;
    int t = row % Tlen;
    const float* h0 = h + (size_t)row * Dm;
    int i = threadIdx.x * 4;
    float4 cur = *(const float4*)(h0 + i);
    float4 w0 = *(const float4*)(cw + 0*Dm + i);
    float4 w1 = *(const float4*)(cw + 1*Dm + i);
    float4 w2 = *(const float4*)(cw + 2*Dm + i);
    float4 bb = *(const float4*)(cb + i);
    float4 z = make_float4(0.f, 0.f, 0.f, 0.f);
    float4 p1 = (t >= 1) ? *(const float4*)(h0 - Dm + i) : z;
    float4 p2 = (t >= 2) ? *(const float4*)(h0 - 2*Dm + i) : z;
    float ox = cur.x + w0.x*p2.x + w1.x*p1.x + w2.x*cur.x + bb.x;
    float oy = cur.y + w0.y*p2.y + w1.y*p1.y + w2.y*cur.y + bb.y;
    float oz = cur.z + w0.z*p2.z + w1.z*p1.z + w2.z*cur.z + bb.z;
    float ow = cur.w + w0.w*p2.w + w1.w*p1.w + w2.w*cur.w + bb.w;
    *(__half2*)(out + (size_t)row * Dm + i)     = __floats2half2_rn(ox, oy);
    *(__half2*)(out + (size_t)row * Dm + i + 2) = __floats2half2_rn(oz, ow);
}

// ---------------- static physics ----------------
__global__ void physics_kernel(const float* __restrict__ W_LTM,
                               const float* __restrict__ V_T0,
                               const float* __restrict__ V_gs,
                               const float* __restrict__ beta_tau,
                               const float* __restrict__ beta_gm,
                               const float* __restrict__ C_ch,
                               const float* __restrict__ gma,
                               const float* __restrict__ alpha,
                               const float* __restrict__ icth,
                               float* __restrict__ ret,
                               float* __restrict__ gate) {
    int idx = blockIdx.x * blockDim.x + threadIdx.x;
    if (idx >= Ll*Hh*DK*DK) return;
    int lh = idx / (DK*DK);
    int l  = lh / Hh;
    float veff = (V_gs[lh] - V_T0[lh]) + W_LTM[idx];
    float sp   = (veff > 20.f) ? veff : log1pf(expf(veff));
    float g_ch = beta_tau[lh] * sp;
    float r    = expf(-g_ch / C_ch[lh]);
    float G    = beta_gm[lh] * sp * (1.f / (1.f + expf(-veff)));
    float sgn  = tanhf(alpha[l] * (g_ch - icth[l]));
    ret[idx]  = r;
    gate[idx] = gma[lh] * sgn * G;
}

// ---------------- scan v4: 256 blocks x 128 thr, f32x2, 8 elems/thread -----
// 16 v-rows x 8 k-parts per block; part handles 8 k-elems = 4 f32x2 pairs.
// f' = r*f + g*(vt*k); y = (w+f).q  (same math as reference, fp32 per lane)
__global__ void __launch_bounds__(128) scan_kernel(const float* __restrict__ qkv,
                                                   const float* __restrict__ ret,
                                                   const float* __restrict__ gate,
                                                   const float* __restrict__ W,
                                                   __half* __restrict__ y) {
    int bh = blockIdx.x >> 2;
    int vq = blockIdx.x & 3;
    int b = bh / Hh, h = bh % Hh;
    int tid = threadIdx.x;
    int v = vq * 16 + (tid >> 3), part = tid & 7, koff = part * 8;

    unsigned long long r2[4], g2[4], w2[4], F2[4];
    {
        int base = (h*DK + v)*DK + koff;
        #pragma unroll
        for (int p = 0; p < 4; p++) {
            r2[p] = pack2(ret[base + 2*p],  ret[base + 2*p + 1]);
            g2[p] = pack2(gate[base + 2*p], gate[base + 2*p + 1]);
            w2[p] = pack2(W[base + 2*p],    W[base + 2*p + 1]);
            F2[p] = pack2(0.f, 0.f);
        }
    }

    __shared__ __align__(16) float sbuf[2][16][192];   // [q(64)|k(64)|v(64)]
    size_t rowbase = (size_t)b * Tlen * (3*Dm) + h * DK;
    // loader A: all 128 threads -> q (tid<64) / k (tid>=64)
    const float* srcA = qkv + rowbase + (size_t)(tid >> 6) * Dm + (tid & 63);
    // loader B: threads 0..63 -> v
    bool hasB = tid < 64;
    const float* srcB = qkv + rowbase + 2*Dm + tid;
    float preA[16], preB[16];
    #pragma unroll
    for (int j = 0; j < 16; j++) {
        preA[j] = srcA[(size_t)j * (3*Dm)];
        preB[j] = hasB ? srcB[(size_t)j * (3*Dm)] : 0.f;
    }
    __half* yout = y + (size_t)b * Tlen * Dm + h * DK + v;

    const int NB = Tlen / 16;
    for (int tb = 0; tb < NB; tb++) {
        int p = tb & 1;
        #pragma unroll
        for (int j = 0; j < 16; j++) {
            sbuf[p][j][tid] = preA[j];
            if (hasB) sbuf[p][j][128 + tid] = preB[j];
        }
        __syncthreads();
        if (tb + 1 < NB) {
            size_t tn = (size_t)(tb * 16 + 16);
            #pragma unroll
            for (int j = 0; j < 16; j++) {
                preA[j] = srcA[(tn + j) * (3*Dm)];
                if (hasB) preB[j] = srcB[(tn + j) * (3*Dm)];
            }
        }
        #pragma unroll
        for (int st = 0; st < 16; st++) {
            float vt = sbuf[p][st][128 + v];
            unsigned long long vt2 = pack2(vt, vt);
            const ulonglong2* kkp = (const ulonglong2*)&sbuf[p][st][64 + koff];
            const ulonglong2* qqp = (const ulonglong2*)&sbuf[p][st][koff];
            ulonglong2 kA = kkp[0], kB = kkp[1];
            ulonglong2 qA = qqp[0], qB = qqp[1];
            unsigned long long kk2[4] = {kA.x, kA.y, kB.x, kB.y};
            unsigned long long qq2[4] = {qA.x, qA.y, qB.x, qB.y};
            unsigned long long y2 = pack2(0.f, 0.f);
            #pragma unroll
            for (int pp = 0; pp < 4; pp++) {
                unsigned long long vtk, gvk, wf;
                MUL2(vtk, vt2, kk2[pp]);
                MUL2(gvk, g2[pp], vtk);
                FMA2(F2[pp], r2[pp], F2[pp], gvk);
                ADD2(wf, w2[pp], F2[pp]);
                FMA2(y2, wf, qq2[pp], y2);
            }
            float ylo, yhi;
            unpack2(y2, ylo, yhi);
            float yacc = ylo + yhi;
            yacc += __shfl_xor_sync(0xffffffffu, yacc, 1);
            yacc += __shfl_xor_sync(0xffffffffu, yacc, 2);
            yacc += __shfl_xor_sync(0xffffffffu, yacc, 4);
            if (part == 0) yout[(size_t)(tb * 16 + st) * Dm] = __float2half_rn(yacc);
        }
    }
}

// ======== shared GEMM building blocks ========
#define SUBT_B  8192
#define SS_B    (2*SUBT_B)
#define NSS     2
#define G_SMEM_BYTES (2*NSS*SS_B)          // 65536

__device__ __forceinline__ void cpasync16(uint32_t dst_smem, const void* src) {
    asm volatile("cp.async.cg.shared.global [%0], [%1], 16;"
                 :: "r"(dst_smem), "l"(src) : "memory");
}
__device__ __forceinline__ uint32_t smem_u32(const void* p) {
    uint32_t a;
    asm("{ .reg .u64 t; cvta.to.shared.u64 t, %1; cvt.u32.u64 %0, t; }"
        : "=r"(a) : "l"(p));
    return a;
}
__device__ __forceinline__ void ldm_x4(uint32_t& r0, uint32_t& r1,
                                       uint32_t& r2, uint32_t& r3, uint32_t addr) {
    asm volatile("ldmatrix.sync.aligned.m8n8.x4.shared.b16 {%0,%1,%2,%3}, [%4];"
                 : "=r"(r0), "=r"(r1), "=r"(r2), "=r"(r3) : "r"(addr));
}
__device__ __forceinline__ void mma_f16(float c[4],
                                        uint32_t a0, uint32_t a1, uint32_t a2, uint32_t a3,
                                        uint32_t b0, uint32_t b1) {
    asm volatile(
        "mma.sync.aligned.m16n8k16.row.col.f32.f16.f16.f32 "
        "{%0,%1,%2,%3}, {%4,%5,%6,%7}, {%8,%9}, {%0,%1,%2,%3};\n"
        : "+f"(c[0]), "+f"(c[1]), "+f"(c[2]), "+f"(c[3])
        : "r"(a0), "r"(a1), "r"(a2), "r"(a3), "r"(b0), "r"(b1));
}

__device__ __forceinline__ void issue_tile128(uint32_t base,
                                              const __half* __restrict__ Gp,
                                              int K, int k0, int tid) {
    #pragma unroll
    for (int hi = 0; hi < 4; hi++) {
        int c = tid + hi * 128;
        int mr = c >> 3, kk = c & 7;
        int m = mr * 2 + (kk >> 2);
        int h0 = (kk & 3) * 8;
        uint32_t dst = base + (uint32_t)(mr * 128 + ((kk ^ (mr & 7)) << 4));
        cpasync16(dst, Gp + (size_t)m * K + k0 + h0);
    }
}
__device__ __forceinline__ void issue_tile64(uint32_t base,
                                             const __half* __restrict__ Gp,
                                             int K, int k0, int tid) {
    #pragma unroll
    for (int hi = 0; hi < 2; hi++) {
        int c = tid + hi * 128;
        int mr = c >> 3, kk = c & 7;
        int m = mr * 2 + (kk >> 2);
        int h0 = (kk & 3) * 8;
        uint32_t dst = base + (uint32_t)(mr * 128 + ((kk ^ (mr & 7)) << 4));
        cpasync16(dst, Gp + (size_t)m * K + k0 + h0);
    }
}

__device__ __forceinline__ void issue_ss(uint32_t sbase, int ss,
                                         const __half* __restrict__ Agp,
                                         const __half* __restrict__ Bgp,
                                         int K, int k0, int tid) {
    uint32_t aB = sbase + (uint32_t)ss * SS_B;
    uint32_t bB = sbase + (uint32_t)(NSS * SS_B) + (uint32_t)ss * SS_B;
    issue_tile128(aB,          Agp, K, k0,      tid);
    issue_tile128(aB + SUBT_B, Agp, K, k0 + 32, tid);
    issue_tile128(bB,          Bgp, K, k0,      tid);
    issue_tile128(bB + SUBT_B, Bgp, K, k0 + 32, tid);
}

// ======== GEMM 128x128 (qkv + head), NSS=2, 3 CTA/SM, fused k-LN ========
__global__ void __launch_bounds__(128, 3) mma_nt_h(int M, int N, int K,
                                                   const __half* __restrict__ A,
                                                   const __half* __restrict__ B,
                                                   const float* __restrict__ Res,
                                                   float* __restrict__ C,
                                                   const float* __restrict__ lng,
                                                   const float* __restrict__ lnb,
                                                   int lnmode) {
    extern __shared__ __half smemh[];
    uint32_t sbase = smem_u32(smemh);
    int tid = threadIdx.x;
    int wid = tid >> 5, lane = tid & 31;
    int wm = (wid & 1) * 64;
    int wn = (wid >> 1) * 64;
    int m0 = blockIdx.y * 128, n0 = blockIdx.x * 128;
    int lg = lane >> 2;
    int lq = lane & 3;

    float acc[4][8][4];
    #pragma unroll
    for (int i = 0; i < 4; i++)
        #pragma unroll
        for (int j = 0; j < 8; j++)
            #pragma unroll
            for (int q = 0; q < 4; q++) acc[i][j][q] = 0.f;

    const __half* Agp = A + (size_t)m0 * K;
    const __half* Bgp = B + (size_t)n0 * K;

    int lm = lane & 15;
    int lc = lane >> 4;
    int mrA0 = (wm + lm) >> 1;
    int mrB0 = (wn + lm) >> 1;
    int halfbit = lm & 1;
    int kpA[2], kpB[2];
    #pragma unroll
    for (int kb = 0; kb < 2; kb++) {
        kpA[kb] = ((halfbit * 4 + kb * 2 + lc) ^ (mrA0 & 7)) << 4;
        kpB[kb] = ((halfbit * 4 + kb * 2 + lc) ^ (mrB0 & 7)) << 4;
    }
    uint32_t aRow = (uint32_t)(mrA0 * 128);
    uint32_t bRow = (uint32_t)(mrB0 * 128);

    int nSS = K >> 6;

    issue_ss(sbase, 0, Agp, Bgp, K, 0,  tid);
    asm volatile("cp.async.commit_group;");
    issue_ss(sbase, 1, Agp, Bgp, K, 64, tid);
    asm volatile("cp.async.commit_group;");

    for (int st = 0; st < nSS; st++) {
        int ss = st & 1;
        asm volatile("cp.async.wait_group 1;");
        __syncthreads();

        uint32_t aSS = sbase + (uint32_t)ss * SS_B + aRow;
        uint32_t bSS = sbase + (uint32_t)(NSS * SS_B) + (uint32_t)ss * SS_B + bRow;

        #pragma unroll
        for (int sub = 0; sub < 2; sub++) {
            uint32_t aBase = aSS + (uint32_t)(sub * SUBT_B);
            uint32_t bBase = bSS + (uint32_t)(sub * SUBT_B);
            #pragma unroll
            for (int kb = 0; kb < 2; kb++) {
                uint32_t af[4][4];
                #pragma unroll
                for (int i = 0; i < 4; i++)
                    ldm_x4(af[i][0], af[i][1], af[i][2], af[i][3],
                           aBase + (uint32_t)(i * 1024) + kpA[kb]);
                #pragma unroll
                for (int jj = 0; jj < 4; jj++) {
                    uint32_t b0, b1, b2, b3;
                    ldm_x4(b0, b1, b2, b3, bBase + (uint32_t)(jj * 1024) + kpB[kb]);
                    #pragma unroll
                    for (int i = 0; i < 4; i++) {
                        mma_f16(acc[i][jj*2],   af[i][0], af[i][1], af[i][2], af[i][3], b0, b2);
                        mma_f16(acc[i][jj*2+1], af[i][0], af[i][1], af[i][2], af[i][3], b1, b3);
                    }
                }
            }
        }
        __syncthreads();
        if (st + 2 < nSS)
            issue_ss(sbase, ss, Agp, Bgp, K, (st + 2) << 6, tid);
        asm volatile("cp.async.commit_group;");
    }

    bool do_ln = (lnmode != 0) && ((n0 + wn) >= Dm) && ((n0 + wn) < 2*Dm);
    #pragma unroll
    for (int i = 0; i < 4; i++) {
        int row = m0 + wm + i*16 + lg;
        float mA = 0.f, rA = 1.f, mB = 0.f, rB = 1.f;
        if (do_ln) {
            float s0 = 0.f, q0 = 0.f, s1 = 0.f, q1 = 0.f;
            #pragma unroll
            for (int j = 0; j < 8; j++) {
                s0 += acc[i][j][0] + acc[i][j][1];
                q0 += acc[i][j][0]*acc[i][j][0] + acc[i][j][1]*acc[i][j][1];
                s1 += acc[i][j][2] + acc[i][j][3];
                q1 += acc[i][j][2]*acc[i][j][2] + acc[i][j][3]*acc[i][j][3];
            }
            s0 += __shfl_xor_sync(0xffffffffu, s0, 1);
            s0 += __shfl_xor_sync(0xffffffffu, s0, 2);
            q0 += __shfl_xor_sync(0xffffffffu, q0, 1);
            q0 += __shfl_xor_sync(0xffffffffu, q0, 2);
            s1 += __shfl_xor_sync(0xffffffffu, s1, 1);
            s1 += __shfl_xor_sync(0xffffffffu, s1, 2);
            q1 += __shfl_xor_sync(0xffffffffu, q1, 1);
            q1 += __shfl_xor_sync(0xffffffffu, q1, 2);
            mA = s0 * (1.f/64);
            rA = rsqrtf(fmaxf(q0 * (1.f/64) - mA*mA, 0.f) + 1e-5f);
            mB = s1 * (1.f/64);
            rB = rsqrtf(fmaxf(q1 * (1.f/64) - mB*mB, 0.f) + 1e-5f);
        }
        #pragma unroll
        for (int j = 0; j < 8; j++) {
            int col = n0 + wn + j*8 + 2*lq;
            size_t o0 = (size_t)row * N + col;
            size_t o1 = (size_t)(row + 8) * N + col;
            float2 v0 = make_float2(acc[i][j][0], acc[i][j][1]);
            float2 v1 = make_float2(acc[i][j][2], acc[i][j][3]);
            if (do_ln) {
                int c = j*8 + 2*lq;
                float g0 = lng[c], b0 = lnb[c];
                float g1 = lng[c+1], b1 = lnb[c+1];
                v0.x = (v0.x - mA)*rA*g0 + b0;  v0.y = (v0.y - mA)*rA*g1 + b1;
                v1.x = (v1.x - mB)*rB*g0 + b0;  v1.y = (v1.y - mB)*rB*g1 + b1;
            }
            if (Res) {
                float2 q0 = *(const float2*)(Res + o0);
                float2 q1 = *(const float2*)(Res + o1);
                v0.x += q0.x; v0.y += q0.y;
                v1.x += q1.x; v1.y += q1.y;
            }
            *(float2*)(C + o0) = v0;
            *(float2*)(C + o1) = v1;
        }
    }
}

// ======== GEMM 64x128 CTA variant (Wo GEMM: better wave balance) ========
#define SUBT_A64  4096
#define SSA_B     (2*SUBT_A64)
#define SSB_B     (2*SUBT_B)
#define G64_SMEM_BYTES (NSS*(SSA_B + SSB_B))  // 49152

__device__ __forceinline__ void issue_ss64(uint32_t sbase, int ss,
                                           const __half* __restrict__ Agp,
                                           const __half* __restrict__ Bgp,
                                           int K, int k0, int tid) {
    uint32_t aB = sbase + (uint32_t)ss * SSA_B;
    uint32_t bB = sbase + (uint32_t)(NSS * SSA_B) + (uint32_t)ss * SSB_B;
    issue_tile64(aB,            Agp, K, k0,      tid);
    issue_tile64(aB + SUBT_A64, Agp, K, k0 + 32, tid);
    issue_tile128(bB,           Bgp, K, k0,      tid);
    issue_tile128(bB + SUBT_B,  Bgp, K, k0 + 32, tid);
}

__global__ void __launch_bounds__(128, 4) mma_nt_64(int M, int N, int K,
                                                    const __half* __restrict__ A,
                                                    const __half* __restrict__ B,
                                                    const float* __restrict__ Res,
                                                    float* __restrict__ C) {
    extern __shared__ __half smemh[];
    uint32_t sbase = smem_u32(smemh);
    int tid = threadIdx.x;
    int wid = tid >> 5, lane = tid & 31;
    int wn = wid * 32;
    int m0 = blockIdx.y * 64, n0 = blockIdx.x * 128;
    int lg = lane >> 2;
    int lq = lane & 3;

    float acc[4][4][4];
    #pragma unroll
    for (int i = 0; i < 4; i++)
        #pragma unroll
        for (int j = 0; j < 4; j++)
            #pragma unroll
            for (int q = 0; q < 4; q++) acc[i][j][q] = 0.f;

    const __half* Agp = A + (size_t)m0 * K;
    const __half* Bgp = B + (size_t)n0 * K;

    int lm = lane & 15;
    int lc = lane >> 4;
    int mrA0 = lm >> 1;
    int mrB0 = (wn + lm) >> 1;
    int halfbit = lm & 1;
    int kpA[2], kpB[2];
    #pragma unroll
    for (int kb = 0; kb < 2; kb++) {
        kpA[kb] = ((halfbit * 4 + kb * 2 + lc) ^ (mrA0 & 7)) << 4;
        kpB[kb] = ((halfbit * 4 + kb * 2 + lc) ^ (mrB0 & 7)) << 4;
    }
    uint32_t aRow = (uint32_t)(mrA0 * 128);
    uint32_t bRow = (uint32_t)(mrB0 * 128);

    int nSS = K >> 6;

    issue_ss64(sbase, 0, Agp, Bgp, K, 0,  tid);
    asm volatile("cp.async.commit_group;");
    issue_ss64(sbase, 1, Agp, Bgp, K, 64, tid);
    asm volatile("cp.async.commit_group;");

    for (int st = 0; st < nSS; st++) {
        int ss = st & 1;
        asm volatile("cp.async.wait_group 1;");
        __syncthreads();

        uint32_t aSS = sbase + (uint32_t)ss * SSA_B + aRow;
        uint32_t bSS = sbase + (uint32_t)(NSS * SSA_B) + (uint32_t)ss * SSB_B + bRow;

        #pragma unroll
        for (int sub = 0; sub < 2; sub++) {
            uint32_t aBase = aSS + (uint32_t)(sub * SUBT_A64);
            uint32_t bBase = bSS + (uint32_t)(sub * SUBT_B);
            #pragma unroll
            for (int kb = 0; kb < 2; kb++) {
                uint32_t af[4][4];
                #pragma unroll
                for (int i = 0; i < 4; i++)
                    ldm_x4(af[i][0], af[i][1], af[i][2], af[i][3],
                           aBase + (uint32_t)(i * 1024) + kpA[kb]);
                #pragma unroll
                for (int jj = 0; jj < 2; jj++) {
                    uint32_t b0, b1, b2, b3;
                    ldm_x4(b0, b1, b2, b3, bBase + (uint32_t)(jj * 1024) + kpB[kb]);
                    #pragma unroll
                    for (int i = 0; i < 4; i++) {
                        mma_f16(acc[i][jj*2],   af[i][0], af[i][1], af[i][2], af[i][3], b0, b2);
                        mma_f16(acc[i][jj*2+1], af[i][0], af[i][1], af[i][2], af[i][3], b1, b3);
                    }
                }
            }
        }
        __syncthreads();
        if (st + 2 < nSS)
            issue_ss64(sbase, ss, Agp, Bgp, K, (st + 2) << 6, tid);
        asm volatile("cp.async.commit_group;");
    }

    #pragma unroll
    for (int i = 0; i < 4; i++) {
        int row = m0 + i*16 + lg;
        #pragma unroll
        for (int j = 0; j < 4; j++) {
            int col = n0 + wn + j*8 + 2*lq;
            size_t o0 = (size_t)row * N + col;
            size_t o1 = (size_t)(row + 8) * N + col;
            float2 v0 = make_float2(acc[i][j][0], acc[i][j][1]);
            float2 v1 = make_float2(acc[i][j][2], acc[i][j][3]);
            if (Res) {
                float2 q0 = *(const float2*)(Res + o0);
                float2 q1 = *(const float2*)(Res + o1);
                v0.x += q0.x; v0.y += q0.y;
                v1.x += q1.x; v1.y += q1.y;
            }
            *(float2*)(C + o0) = v0;
            *(float2*)(C + o1) = v1;
        }
    }
}

// ---------------- launch ----------------
extern "C" void kernel_launch(void* const* d_in, const int* in_sizes, int n_in,
                              void* d_out, int out_size) {
    const int*   ids      = (const int*)  d_in[0];
    const float* embedW   = (const float*)d_in[2];
    const float* conv_w   = (const float*)d_in[3];
    const float* conv_b   = (const float*)d_in[4];
    const float* Wqkv     = (const float*)d_in[5];
    const float* Wo       = (const float*)d_in[6];
    const float* W_LTM    = (const float*)d_in[7];
    const float* V_T0     = (const float*)d_in[8];
    const float* V_gs     = (const float*)d_in[9];
    const float* beta_tau = (const float*)d_in[10];
    const float* beta_gm  = (const float*)d_in[11];
    const float* C_ch     = (const float*)d_in[12];
    const float* gma      = (const float*)d_in[13];
    const float* alpha    = (const float*)d_in[14];
    const float* icth     = (const float*)d_in[15];
    const float* ln1_g    = (const float*)d_in[16];
    const float* ln1_b    = (const float*)d_in[17];
    const float* lnk_g    = (const float*)d_in[18];
    const float* lnk_b    = (const float*)d_in[19];
    const float* lnf_g    = (const float*)d_in[20];
    const float* lnf_b    = (const float*)d_in[21];
    const float* headW    = (const float*)d_in[22];
    float* out = (float*)d_out;

    float *x, *h, *qkv, *ret, *gate;
    __half *h2h, *yh, *hh, *wqh, *woh, *whh;
    cudaGetSymbolAddress((void**)&x,    g_x);
    cudaGetSymbolAddress((void**)&h,    g_h);
    cudaGetSymbolAddress((void**)&h2h,  g_h2h);
    cudaGetSymbolAddress((void**)&qkv,  g_qkv);
    cudaGetSymbolAddress((void**)&yh,   g_yh);
    cudaGetSymbolAddress((void**)&hh,   g_hh);
    cudaGetSymbolAddress((void**)&ret,  g_ret);
    cudaGetSymbolAddress((void**)&gate, g_gate);
    cudaGetSymbolAddress((void**)&wqh,  g_wqh);
    cudaGetSymbolAddress((void**)&woh,  g_woh);
    cudaGetSymbolAddress((void**)&whh,  g_whh);

    cudaFuncSetAttribute(mma_nt_h, cudaFuncAttributeMaxDynamicSharedMemorySize,
                         G_SMEM_BYTES);
    cudaFuncSetAttribute(mma_nt_64, cudaFuncAttributeMaxDynamicSharedMemorySize,
                         G64_SMEM_BYTES);

    {
        long long total = (long long)S1 + S2 + S3;
        int blocks = (int)(total / 1024);
        tohalf_all<<<blocks, 256>>>(Wqkv, Wo, headW, wqh, woh, whh);
    }

    embed_ln_kernel<<<NROW, 256>>>(ids, embedW, ln1_g, ln1_b, x, h);
    {
        int n = Ll*Hh*DK*DK;
        physics_kernel<<<(n + 255)/256, 256>>>(W_LTM, V_T0, V_gs, beta_tau, beta_gm,
                                               C_ch, gma, alpha, icth, ret, gate);
    }

    for (int l = 0; l < Ll; l++) {
        if (l > 0)
            ln_kernel<<<NROW, 256>>>(x, ln1_g + l*Dm, ln1_b + l*Dm, h);
        conv_kernel<<<NROW, 256>>>(h, conv_w + l*3*Dm, conv_b + l*Dm, h2h);

        dim3 gq((3*Dm)/128, NROW/128);
        mma_nt_h<<<gq, 128, G_SMEM_BYTES>>>(NROW, 3*Dm, Dm, h2h,
                                            wqh + (size_t)l*3*Dm*Dm, nullptr, qkv,
                                            lnk_g + l*DK, lnk_b + l*DK, 1);

        scan_kernel<<<Bb*Hh*4, 128>>>(qkv,
                                      ret  + (size_t)l*Hh*DK*DK,
                                      gate + (size_t)l*Hh*DK*DK,
                                      W_LTM + (size_t)l*Hh*DK*DK,
                                      yh);

        dim3 go(Dm/128, NROW/64);
        mma_nt_64<<<go, 128, G64_SMEM_BYTES>>>(NROW, Dm, Dm, yh,
                                               woh + (size_t)l*Dm*Dm, x, x);
    }

    lnh_kernel<<<NROW, 256>>>(x, lnf_g, lnf_b, hh);
    dim3 gh(Vv/128, NROW/128);
    mma_nt_h<<<gh, 128, G_SMEM_BYTES>>>(NROW, Vv, Dm, hh, whh, nullptr, out,
                                        nullptr, nullptr, 0);
}

// round 16
// speedup vs baseline: 1.0757x; 1.0757x over previous
#include <cuda_runtime.h>
#include <cuda_fp16.h>
#include <math.h>
#include <stdint.h>

// ---------------- problem constants ----------------
#define Dm    1024
#define Tlen  2048
#define Bb    4
#define Hh    16
#define DK    64
#define Ll    2
#define Vv    8192
#define NROW  (Bb*Tlen)          // 8192 token rows

// ---------------- scratch (device globals; no allocation allowed) ----------
__device__ float  g_x  [NROW*Dm];
__device__ float  g_h  [NROW*Dm];
__device__ __half g_h2h[NROW*Dm];
__device__ float  g_qkv[NROW*3*Dm];
__device__ __half g_yh [NROW*Dm];
__device__ __half g_hh [NROW*Dm];
__device__ float  g_ret [Ll*Hh*DK*DK];
__device__ float  g_gate[Ll*Hh*DK*DK];
__device__ __half g_wqh[Ll*3*Dm*Dm];
__device__ __half g_woh[Ll*Dm*Dm];
__device__ __half g_whh[Vv*Dm];

// ---------------- merged fp32 -> fp16 weight conversion ----------------
#define S1 (Ll*3*Dm*Dm)
#define S2 (Ll*Dm*Dm)
#define S3 (Vv*Dm)
__global__ void __launch_bounds__(256) tohalf_all(const float* __restrict__ wq,
                                                  const float* __restrict__ wo,
                                                  const float* __restrict__ wh,
                                                  __half* __restrict__ dq,
                                                  __half* __restrict__ dol,
                                                  __half* __restrict__ dh) {
    long long i = (long long)(blockIdx.x * blockDim.x + threadIdx.x) * 4;
    const float* s; __half* d; long long off;
    if (i < S1)            { s = wq; d = dq;  off = i; }
    else if (i < S1 + S2)  { s = wo; d = dol; off = i - S1; }
    else                   { s = wh; d = dh;  off = i - S1 - S2; }
    float4 v = *(const float4*)(s + off);
    *(__half2*)(d + off)     = __floats2half2_rn(v.x, v.y);
    *(__half2*)(d + off + 2) = __floats2half2_rn(v.z, v.w);
}

// ---------------- block reduce helper (blockDim == 256) ----------------
__device__ __forceinline__ float blockReduceSum(float v, float* sh) {
    #pragma unroll
    for (int o = 16; o; o >>= 1) v += __shfl_xor_sync(0xffffffffu, v, o);
    if ((threadIdx.x & 31) == 0) sh[threadIdx.x >> 5] = v;
    __syncthreads();
    float tot = 0.f;
    #pragma unroll
    for (int i = 0; i < 8; i++) tot += sh[i];
    __syncthreads();
    return tot;
}

// ---------------- fused embedding gather + layer-0 LN ----------------
__global__ void __launch_bounds__(256) embed_ln_kernel(const int* __restrict__ ids,
                                                       const float* __restrict__ W,
                                                       const float* __restrict__ g,
                                                       const float* __restrict__ b,
                                                       float* __restrict__ x,
                                                       float* __restrict__ h) {
    __shared__ float sh[8];
    int row = blockIdx.x;
    int id  = ids[row];
    const float* xr = W + (size_t)id * Dm;
    int i0 = threadIdx.x * 4;
    float4 xv = *(const float4*)(xr + i0);
    *(float4*)(x + (size_t)row * Dm + i0) = xv;
    float s = xv.x + xv.y + xv.z + xv.w;
    float mean = blockReduceSum(s, sh) * (1.f / Dm);
    float d0 = xv.x - mean, d1 = xv.y - mean, d2 = xv.z - mean, d3 = xv.w - mean;
    float sq = d0*d0 + d1*d1 + d2*d2 + d3*d3;
    float var = blockReduceSum(sq, sh) * (1.f / Dm);
    float rstd = rsqrtf(var + 1e-5f);
    float4 gv = *(const float4*)(g + i0);
    float4 bv = *(const float4*)(b + i0);
    float4 ov;
    ov.x = d0 * rstd * gv.x + bv.x;
    ov.y = d1 * rstd * gv.y + bv.y;
    ov.z = d2 * rstd * gv.z + bv.z;
    ov.w = d3 * rstd * gv.w + bv.w;
    *(float4*)(h + (size_t)row * Dm + i0) = ov;
}

// ---------------- layernorm (fp32 out) ----------------
__global__ void __launch_bounds__(256) ln_kernel(const float* __restrict__ x,
                                                 const float* __restrict__ g,
                                                 const float* __restrict__ b,
                                                 float* __restrict__ out) {
    __shared__ float sh[8];
    int row = blockIdx.x;
    const float* xr = x + (size_t)row * Dm;
    int i0 = threadIdx.x * 4;
    float4 xv = *(const float4*)(xr + i0);
    float s = xv.x + xv.y + xv.z + xv.w;
    float mean = blockReduceSum(s, sh) * (1.f / Dm);
    float d0 = xv.x - mean, d1 = xv.y - mean, d2 = xv.z - mean, d3 = xv.w - mean;
    float sq = d0*d0 + d1*d1 + d2*d2 + d3*d3;
    float var = blockReduceSum(sq, sh) * (1.f / Dm);
    float rstd = rsqrtf(var + 1e-5f);
    float4 gv = *(const float4*)(g + i0);
    float4 bv = *(const float4*)(b + i0);
    float4 ov;
    ov.x = d0 * rstd * gv.x + bv.x;
    ov.y = d1 * rstd * gv.y + bv.y;
    ov.z = d2 * rstd * gv.z + bv.z;
    ov.w = d3 * rstd * gv.w + bv.w;
    *(float4*)(out + (size_t)row * Dm + i0) = ov;
}

// ---------------- layernorm (half out, for head GEMM A) ----------------
__global__ void __launch_bounds__(256) lnh_kernel(const float* __restrict__ x,
                                                  const float* __restrict__ g,
                                                  const float* __restrict__ b,
                                                  __half* __restrict__ out) {
    __shared__ float sh[8];
    int row = blockIdx.x;
    const float* xr = x + (size_t)row * Dm;
    int i0 = threadIdx.x * 4;
    float4 xv = *(const float4*)(xr + i0);
    float s = xv.x + xv.y + xv.z + xv.w;
    float mean = blockReduceSum(s, sh) * (1.f / Dm);
    float d0 = xv.x - mean, d1 = xv.y - mean, d2 = xv.z - mean, d3 = xv.w - mean;
    float sq = d0*d0 + d1*d1 + d2*d2 + d3*d3;
    float var = blockReduceSum(sq, sh) * (1.f / Dm);
    float rstd = rsqrtf(var + 1e-5f);
    float4 gv = *(const float4*)(g + i0);
    float4 bv = *(const float4*)(b + i0);
    *(__half2*)(out + (size_t)row * Dm + i0) =
        __floats2half2_rn(d0 * rstd * gv.x + bv.x, d1 * rstd * gv.y + bv.y);
    *(__half2*)(out + (size_t)row * Dm + i0 + 2) =
        __floats2half2_rn(d2 * rstd * gv.z + bv.z, d3 * rstd * gv.w + bv.w);
}

// ---------------- causal depthwise conv (half out) ----------------
__global__ void __launch_bounds__(256) conv_kernel(const float* __restrict__ h,
                                                   const float* __restrict__ cw,
                                                   const float* __restrict__ cb,
                                                   __half* __restrict__ out) {
    int row = blockIdx.x;
    int t = row % Tlen;
    const float* h0 = h + (size_t)row * Dm;
    int i = threadIdx.x * 4;
    float4 cur = *(const float4*)(h0 + i);
    float4 w0 = *(const float4*)(cw + 0*Dm + i);
    float4 w1 = *(const float4*)(cw + 1*Dm + i);
    float4 w2 = *(const float4*)(cw + 2*Dm + i);
    float4 bb = *(const float4*)(cb + i);
    float4 z = make_float4(0.f, 0.f, 0.f, 0.f);
    float4 p1 = (t >= 1) ? *(const float4*)(h0 - Dm + i) : z;
    float4 p2 = (t >= 2) ? *(const float4*)(h0 - 2*Dm + i) : z;
    float ox = cur.x + w0.x*p2.x + w1.x*p1.x + w2.x*cur.x + bb.x;
    float oy = cur.y + w0.y*p2.y + w1.y*p1.y + w2.y*cur.y + bb.y;
    float oz = cur.z + w0.z*p2.z + w1.z*p1.z + w2.z*cur.z + bb.z;
    float ow = cur.w + w0.w*p2.w + w1.w*p1.w + w2.w*cur.w + bb.w;
    *(__half2*)(out + (size_t)row * Dm + i)     = __floats2half2_rn(ox, oy);
    *(__half2*)(out + (size_t)row * Dm + i + 2) = __floats2half2_rn(oz, ow);
}

// ---------------- static physics ----------------
__global__ void physics_kernel(const float* __restrict__ W_LTM,
                               const float* __restrict__ V_T0,
                               const float* __restrict__ V_gs,
                               const float* __restrict__ beta_tau,
                               const float* __restrict__ beta_gm,
                               const float* __restrict__ C_ch,
                               const float* __restrict__ gma,
                               const float* __restrict__ alpha,
                               const float* __restrict__ icth,
                               float* __restrict__ ret,
                               float* __restrict__ gate) {
    int idx = blockIdx.x * blockDim.x + threadIdx.x;
    if (idx >= Ll*Hh*DK*DK) return;
    int lh = idx / (DK*DK);
    int l  = lh / Hh;
    float veff = (V_gs[lh] - V_T0[lh]) + W_LTM[idx];
    float sp   = (veff > 20.f) ? veff : log1pf(expf(veff));
    float g_ch = beta_tau[lh] * sp;
    float r    = expf(-g_ch / C_ch[lh]);
    float G    = beta_gm[lh] * sp * (1.f / (1.f + expf(-veff)));
    float sgn  = tanhf(alpha[l] * (g_ch - icth[l]));
    ret[idx]  = r;
    gate[idx] = gma[lh] * sgn * G;
}

// ---------------- scan v2 @ 2 CTA/SM: 256 blocks run in ONE wave -----------
__global__ void __launch_bounds__(256, 2) scan_kernel(const float* __restrict__ qkv,
                                                      const float* __restrict__ ret,
                                                      const float* __restrict__ gate,
                                                      const float* __restrict__ W,
                                                      __half* __restrict__ y) {
    int bh = blockIdx.x >> 2;
    int vq = blockIdx.x & 3;
    int b = bh / Hh, h = bh % Hh;
    int tid = threadIdx.x;
    int v = vq * 16 + (tid >> 4), part = tid & 15, koff = part * 4;

    float r[4], g[4], w[4], f[4];
    {
        int base = (h*DK + v)*DK + koff;
        #pragma unroll
        for (int j = 0; j < 4; j++) {
            r[j] = ret[base + j];
            g[j] = gate[base + j];
            w[j] = W[base + j];
            f[j] = 0.f;
        }
    }

    __shared__ float sbuf[2][16][192];
    bool loader = tid < 192;
    int which = tid >> 6, lane = tid & 63;
    size_t rowbase = (size_t)b * Tlen * (3*Dm) + h * DK;
    const float* src = qkv + rowbase + which * Dm + lane;
    float pre[16];
    if (loader) {
        #pragma unroll
        for (int j = 0; j < 16; j++) pre[j] = src[(size_t)j * (3*Dm)];
    }
    __half* yout = y + (size_t)b * Tlen * Dm + h * DK + v;

    const int NB = Tlen / 16;
    for (int tb = 0; tb < NB; tb++) {
        int p = tb & 1;
        if (loader) {
            #pragma unroll
            for (int j = 0; j < 16; j++) sbuf[p][j][tid] = pre[j];
        }
        __syncthreads();
        if (loader && tb + 1 < NB) {
            size_t tn = (size_t)(tb * 16 + 16);
            #pragma unroll
            for (int j = 0; j < 16; j++)
                pre[j] = src[(tn + j) * (3*Dm)];
        }
        #pragma unroll
        for (int st = 0; st < 16; st++) {
            float vt = sbuf[p][st][128 + v];
            float4 kk = *(const float4*)&sbuf[p][st][64 + koff];
            float4 qq = *(const float4*)&sbuf[p][st][koff];
            f[0] = r[0]*f[0] + (g[0]*vt)*kk.x;
            f[1] = r[1]*f[1] + (g[1]*vt)*kk.y;
            f[2] = r[2]*f[2] + (g[2]*vt)*kk.z;
            f[3] = r[3]*f[3] + (g[3]*vt)*kk.w;
            float yacc;
            yacc = (w[0] + f[0]) * qq.x;
            yacc = fmaf(w[1] + f[1], qq.y, yacc);
            yacc = fmaf(w[2] + f[2], qq.z, yacc);
            yacc = fmaf(w[3] + f[3], qq.w, yacc);
            yacc += __shfl_xor_sync(0xffffffffu, yacc, 1);
            yacc += __shfl_xor_sync(0xffffffffu, yacc, 2);
            yacc += __shfl_xor_sync(0xffffffffu, yacc, 4);
            yacc += __shfl_xor_sync(0xffffffffu, yacc, 8);
            if (part == 0) yout[(size_t)(tb * 16 + st) * Dm] = __float2half_rn(yacc);
        }
    }
}

// ======== shared GEMM building blocks ========
#define SUBT_B  8192
#define SS_B    (2*SUBT_B)
#define NSS     2
#define G_SMEM_BYTES (2*NSS*SS_B)          // 65536

__device__ __forceinline__ void cpasync16(uint32_t dst_smem, const void* src) {
    asm volatile("cp.async.cg.shared.global [%0], [%1], 16;"
                 :: "r"(dst_smem), "l"(src) : "memory");
}
__device__ __forceinline__ uint32_t smem_u32(const void* p) {
    uint32_t a;
    asm("{ .reg .u64 t; cvta.to.shared.u64 t, %1; cvt.u32.u64 %0, t; }"
        : "=r"(a) : "l"(p));
    return a;
}
__device__ __forceinline__ void ldm_x4(uint32_t& r0, uint32_t& r1,
                                       uint32_t& r2, uint32_t& r3, uint32_t addr) {
    asm volatile("ldmatrix.sync.aligned.m8n8.x4.shared.b16 {%0,%1,%2,%3}, [%4];"
                 : "=r"(r0), "=r"(r1), "=r"(r2), "=r"(r3) : "r"(addr));
}
__device__ __forceinline__ void mma_f16(float c[4],
                                        uint32_t a0, uint32_t a1, uint32_t a2, uint32_t a3,
                                        uint32_t b0, uint32_t b1) {
    asm volatile(
        "mma.sync.aligned.m16n8k16.row.col.f32.f16.f16.f32 "
        "{%0,%1,%2,%3}, {%4,%5,%6,%7}, {%8,%9}, {%0,%1,%2,%3};\n"
        : "+f"(c[0]), "+f"(c[1]), "+f"(c[2]), "+f"(c[3])
        : "r"(a0), "r"(a1), "r"(a2), "r"(a3), "r"(b0), "r"(b1));
}

__device__ __forceinline__ void issue_tile128(uint32_t base,
                                              const __half* __restrict__ Gp,
                                              int K, int k0, int tid) {
    #pragma unroll
    for (int hi = 0; hi < 4; hi++) {
        int c = tid + hi * 128;
        int mr = c >> 3, kk = c & 7;
        int m = mr * 2 + (kk >> 2);
        int h0 = (kk & 3) * 8;
        uint32_t dst = base + (uint32_t)(mr * 128 + ((kk ^ (mr & 7)) << 4));
        cpasync16(dst, Gp + (size_t)m * K + k0 + h0);
    }
}
__device__ __forceinline__ void issue_tile64(uint32_t base,
                                             const __half* __restrict__ Gp,
                                             int K, int k0, int tid) {
    #pragma unroll
    for (int hi = 0; hi < 2; hi++) {
        int c = tid + hi * 128;
        int mr = c >> 3, kk = c & 7;
        int m = mr * 2 + (kk >> 2);
        int h0 = (kk & 3) * 8;
        uint32_t dst = base + (uint32_t)(mr * 128 + ((kk ^ (mr & 7)) << 4));
        cpasync16(dst, Gp + (size_t)m * K + k0 + h0);
    }
}

__device__ __forceinline__ void issue_ss(uint32_t sbase, int ss,
                                         const __half* __restrict__ Agp,
                                         const __half* __restrict__ Bgp,
                                         int K, int k0, int tid) {
    uint32_t aB = sbase + (uint32_t)ss * SS_B;
    uint32_t bB = sbase + (uint32_t)(NSS * SS_B) + (uint32_t)ss * SS_B;
    issue_tile128(aB,          Agp, K, k0,      tid);
    issue_tile128(aB + SUBT_B, Agp, K, k0 + 32, tid);
    issue_tile128(bB,          Bgp, K, k0,      tid);
    issue_tile128(bB + SUBT_B, Bgp, K, k0 + 32, tid);
}

// ======== GEMM 128x128 (qkv + head), NSS=2, 3 CTA/SM, fused k-LN ========
__global__ void __launch_bounds__(128, 3) mma_nt_h(int M, int N, int K,
                                                   const __half* __restrict__ A,
                                                   const __half* __restrict__ B,
                                                   const float* __restrict__ Res,
                                                   float* __restrict__ C,
                                                   const float* __restrict__ lng,
                                                   const float* __restrict__ lnb,
                                                   int lnmode) {
    extern __shared__ __half smemh[];
    uint32_t sbase = smem_u32(smemh);
    int tid = threadIdx.x;
    int wid = tid >> 5, lane = tid & 31;
    int wm = (wid & 1) * 64;
    int wn = (wid >> 1) * 64;
    int m0 = blockIdx.y * 128, n0 = blockIdx.x * 128;
    int lg = lane >> 2;
    int lq = lane & 3;

    float acc[4][8][4];
    #pragma unroll
    for (int i = 0; i < 4; i++)
        #pragma unroll
        for (int j = 0; j < 8; j++)
            #pragma unroll
            for (int q = 0; q < 4; q++) acc[i][j][q] = 0.f;

    const __half* Agp = A + (size_t)m0 * K;
    const __half* Bgp = B + (size_t)n0 * K;

    int lm = lane & 15;
    int lc = lane >> 4;
    int mrA0 = (wm + lm) >> 1;
    int mrB0 = (wn + lm) >> 1;
    int halfbit = lm & 1;
    int kpA[2], kpB[2];
    #pragma unroll
    for (int kb = 0; kb < 2; kb++) {
        kpA[kb] = ((halfbit * 4 + kb * 2 + lc) ^ (mrA0 & 7)) << 4;
        kpB[kb] = ((halfbit * 4 + kb * 2 + lc) ^ (mrB0 & 7)) << 4;
    }
    uint32_t aRow = (uint32_t)(mrA0 * 128);
    uint32_t bRow = (uint32_t)(mrB0 * 128);

    int nSS = K >> 6;

    issue_ss(sbase, 0, Agp, Bgp, K, 0,  tid);
    asm volatile("cp.async.commit_group;");
    issue_ss(sbase, 1, Agp, Bgp, K, 64, tid);
    asm volatile("cp.async.commit_group;");

    for (int st = 0; st < nSS; st++) {
        int ss = st & 1;
        asm volatile("cp.async.wait_group 1;");
        __syncthreads();

        uint32_t aSS = sbase + (uint32_t)ss * SS_B + aRow;
        uint32_t bSS = sbase + (uint32_t)(NSS * SS_B) + (uint32_t)ss * SS_B + bRow;

        #pragma unroll
        for (int sub = 0; sub < 2; sub++) {
            uint32_t aBase = aSS + (uint32_t)(sub * SUBT_B);
            uint32_t bBase = bSS + (uint32_t)(sub * SUBT_B);
            #pragma unroll
            for (int kb = 0; kb < 2; kb++) {
                uint32_t af[4][4];
                #pragma unroll
                for (int i = 0; i < 4; i++)
                    ldm_x4(af[i][0], af[i][1], af[i][2], af[i][3],
                           aBase + (uint32_t)(i * 1024) + kpA[kb]);
                #pragma unroll
                for (int jj = 0; jj < 4; jj++) {
                    uint32_t b0, b1, b2, b3;
                    ldm_x4(b0, b1, b2, b3, bBase + (uint32_t)(jj * 1024) + kpB[kb]);
                    #pragma unroll
                    for (int i = 0; i < 4; i++) {
                        mma_f16(acc[i][jj*2],   af[i][0], af[i][1], af[i][2], af[i][3], b0, b2);
                        mma_f16(acc[i][jj*2+1], af[i][0], af[i][1], af[i][2], af[i][3], b1, b3);
                    }
                }
            }
        }
        __syncthreads();
        if (st + 2 < nSS)
            issue_ss(sbase, ss, Agp, Bgp, K, (st + 2) << 6, tid);
        asm volatile("cp.async.commit_group;");
    }

    bool do_ln = (lnmode != 0) && ((n0 + wn) >= Dm) && ((n0 + wn) < 2*Dm);
    #pragma unroll
    for (int i = 0; i < 4; i++) {
        int row = m0 + wm + i*16 + lg;
        float mA = 0.f, rA = 1.f, mB = 0.f, rB = 1.f;
        if (do_ln) {
            float s0 = 0.f, q0 = 0.f, s1 = 0.f, q1 = 0.f;
            #pragma unroll
            for (int j = 0; j < 8; j++) {
                s0 += acc[i][j][0] + acc[i][j][1];
                q0 += acc[i][j][0]*acc[i][j][0] + acc[i][j][1]*acc[i][j][1];
                s1 += acc[i][j][2] + acc[i][j][3];
                q1 += acc[i][j][2]*acc[i][j][2] + acc[i][j][3]*acc[i][j][3];
            }
            s0 += __shfl_xor_sync(0xffffffffu, s0, 1);
            s0 += __shfl_xor_sync(0xffffffffu, s0, 2);
            q0 += __shfl_xor_sync(0xffffffffu, q0, 1);
            q0 += __shfl_xor_sync(0xffffffffu, q0, 2);
            s1 += __shfl_xor_sync(0xffffffffu, s1, 1);
            s1 += __shfl_xor_sync(0xffffffffu, s1, 2);
            q1 += __shfl_xor_sync(0xffffffffu, q1, 1);
            q1 += __shfl_xor_sync(0xffffffffu, q1, 2);
            mA = s0 * (1.f/64);
            rA = rsqrtf(fmaxf(q0 * (1.f/64) - mA*mA, 0.f) + 1e-5f);
            mB = s1 * (1.f/64);
            rB = rsqrtf(fmaxf(q1 * (1.f/64) - mB*mB, 0.f) + 1e-5f);
        }
        #pragma unroll
        for (int j = 0; j < 8; j++) {
            int col = n0 + wn + j*8 + 2*lq;
            size_t o0 = (size_t)row * N + col;
            size_t o1 = (size_t)(row + 8) * N + col;
            float2 v0 = make_float2(acc[i][j][0], acc[i][j][1]);
            float2 v1 = make_float2(acc[i][j][2], acc[i][j][3]);
            if (do_ln) {
                int c = j*8 + 2*lq;
                float g0 = lng[c], b0 = lnb[c];
                float g1 = lng[c+1], b1 = lnb[c+1];
                v0.x = (v0.x - mA)*rA*g0 + b0;  v0.y = (v0.y - mA)*rA*g1 + b1;
                v1.x = (v1.x - mB)*rB*g0 + b0;  v1.y = (v1.y - mB)*rB*g1 + b1;
            }
            if (Res) {
                float2 q0 = *(const float2*)(Res + o0);
                float2 q1 = *(const float2*)(Res + o1);
                v0.x += q0.x; v0.y += q0.y;
                v1.x += q1.x; v1.y += q1.y;
            }
            *(float2*)(C + o0) = v0;
            *(float2*)(C + o1) = v1;
        }
    }
}

// ======== GEMM 64x128 CTA variant (Wo GEMM: better wave balance) ========
#define SUBT_A64  4096
#define SSA_B     (2*SUBT_A64)
#define SSB_B     (2*SUBT_B)
#define G64_SMEM_BYTES (NSS*(SSA_B + SSB_B))  // 49152

__device__ __forceinline__ void issue_ss64(uint32_t sbase, int ss,
                                           const __half* __restrict__ Agp,
                                           const __half* __restrict__ Bgp,
                                           int K, int k0, int tid) {
    uint32_t aB = sbase + (uint32_t)ss * SSA_B;
    uint32_t bB = sbase + (uint32_t)(NSS * SSA_B) + (uint32_t)ss * SSB_B;
    issue_tile64(aB,            Agp, K, k0,      tid);
    issue_tile64(aB + SUBT_A64, Agp, K, k0 + 32, tid);
    issue_tile128(bB,           Bgp, K, k0,      tid);
    issue_tile128(bB + SUBT_B,  Bgp, K, k0 + 32, tid);
}

__global__ void __launch_bounds__(128, 4) mma_nt_64(int M, int N, int K,
                                                    const __half* __restrict__ A,
                                                    const __half* __restrict__ B,
                                                    const float* __restrict__ Res,
                                                    float* __restrict__ C) {
    extern __shared__ __half smemh[];
    uint32_t sbase = smem_u32(smemh);
    int tid = threadIdx.x;
    int wid = tid >> 5, lane = tid & 31;
    int wn = wid * 32;
    int m0 = blockIdx.y * 64, n0 = blockIdx.x * 128;
    int lg = lane >> 2;
    int lq = lane & 3;

    float acc[4][4][4];
    #pragma unroll
    for (int i = 0; i < 4; i++)
        #pragma unroll
        for (int j = 0; j < 4; j++)
            #pragma unroll
            for (int q = 0; q < 4; q++) acc[i][j][q] = 0.f;

    const __half* Agp = A + (size_t)m0 * K;
    const __half* Bgp = B + (size_t)n0 * K;

    int lm = lane & 15;
    int lc = lane >> 4;
    int mrA0 = lm >> 1;
    int mrB0 = (wn + lm) >> 1;
    int halfbit = lm & 1;
    int kpA[2], kpB[2];
    #pragma unroll
    for (int kb = 0; kb < 2; kb++) {
        kpA[kb] = ((halfbit * 4 + kb * 2 + lc) ^ (mrA0 & 7)) << 4;
        kpB[kb] = ((halfbit * 4 + kb * 2 + lc) ^ (mrB0 & 7)) << 4;
    }
    uint32_t aRow = (uint32_t)(mrA0 * 128);
    uint32_t bRow = (uint32_t)(mrB0 * 128);

    int nSS = K >> 6;

    issue_ss64(sbase, 0, Agp, Bgp, K, 0,  tid);
    asm volatile("cp.async.commit_group;");
    issue_ss64(sbase, 1, Agp, Bgp, K, 64, tid);
    asm volatile("cp.async.commit_group;");

    for (int st = 0; st < nSS; st++) {
        int ss = st & 1;
        asm volatile("cp.async.wait_group 1;");
        __syncthreads();

        uint32_t aSS = sbase + (uint32_t)ss * SSA_B + aRow;
        uint32_t bSS = sbase + (uint32_t)(NSS * SSA_B) + (uint32_t)ss * SSB_B + bRow;

        #pragma unroll
        for (int sub = 0; sub < 2; sub++) {
            uint32_t aBase = aSS + (uint32_t)(sub * SUBT_A64);
            uint32_t bBase = bSS + (uint32_t)(sub * SUBT_B);
            #pragma unroll
            for (int kb = 0; kb < 2; kb++) {
                uint32_t af[4][4];
                #pragma unroll
                for (int i = 0; i < 4; i++)
                    ldm_x4(af[i][0], af[i][1], af[i][2], af[i][3],
                           aBase + (uint32_t)(i * 1024) + kpA[kb]);
                #pragma unroll
                for (int jj = 0; jj < 2; jj++) {
                    uint32_t b0, b1, b2, b3;
                    ldm_x4(b0, b1, b2, b3, bBase + (uint32_t)(jj * 1024) + kpB[kb]);
                    #pragma unroll
                    for (int i = 0; i < 4; i++) {
                        mma_f16(acc[i][jj*2],   af[i][0], af[i][1], af[i][2], af[i][3], b0, b2);
                        mma_f16(acc[i][jj*2+1], af[i][0], af[i][1], af[i][2], af[i][3], b1, b3);
                    }
                }
            }
        }
        __syncthreads();
        if (st + 2 < nSS)
            issue_ss64(sbase, ss, Agp, Bgp, K, (st + 2) << 6, tid);
        asm volatile("cp.async.commit_group;");
    }

    #pragma unroll
    for (int i = 0; i < 4; i++) {
        int row = m0 + i*16 + lg;
        #pragma unroll
        for (int j = 0; j < 4; j++) {
            int col = n0 + wn + j*8 + 2*lq;
            size_t o0 = (size_t)row * N + col;
            size_t o1 = (size_t)(row + 8) * N + col;
            float2 v0 = make_float2(acc[i][j][0], acc[i][j][1]);
            float2 v1 = make_float2(acc[i][j][2], acc[i][j][3]);
            if (Res) {
                float2 q0 = *(const float2*)(Res + o0);
                float2 q1 = *(const float2*)(Res + o1);
                v0.x += q0.x; v0.y += q0.y;
                v1.x += q1.x; v1.y += q1.y;
            }
            *(float2*)(C + o0) = v0;
            *(float2*)(C + o1) = v1;
        }
    }
}

// ---------------- launch ----------------
extern "C" void kernel_launch(void* const* d_in, const int* in_sizes, int n_in,
                              void* d_out, int out_size) {
    const int*   ids      = (const int*)  d_in[0];
    const float* embedW   = (const float*)d_in[2];
    const float* conv_w   = (const float*)d_in[3];
    const float* conv_b   = (const float*)d_in[4];
    const float* Wqkv     = (const float*)d_in[5];
    const float* Wo       = (const float*)d_in[6];
    const float* W_LTM    = (const float*)d_in[7];
    const float* V_T0     = (const float*)d_in[8];
    const float* V_gs     = (const float*)d_in[9];
    const float* beta_tau = (const float*)d_in[10];
    const float* beta_gm  = (const float*)d_in[11];
    const float* C_ch     = (const float*)d_in[12];
    const float* gma      = (const float*)d_in[13];
    const float* alpha    = (const float*)d_in[14];
    const float* icth     = (const float*)d_in[15];
    const float* ln1_g    = (const float*)d_in[16];
    const float* ln1_b    = (const float*)d_in[17];
    const float* lnk_g    = (const float*)d_in[18];
    const float* lnk_b    = (const float*)d_in[19];
    const float* lnf_g    = (const float*)d_in[20];
    const float* lnf_b    = (const float*)d_in[21];
    const float* headW    = (const float*)d_in[22];
    float* out = (float*)d_out;

    float *x, *h, *qkv, *ret, *gate;
    __half *h2h, *yh, *hh, *wqh, *woh, *whh;
    cudaGetSymbolAddress((void**)&x,    g_x);
    cudaGetSymbolAddress((void**)&h,    g_h);
    cudaGetSymbolAddress((void**)&h2h,  g_h2h);
    cudaGetSymbolAddress((void**)&qkv,  g_qkv);
    cudaGetSymbolAddress((void**)&yh,   g_yh);
    cudaGetSymbolAddress((void**)&hh,   g_hh);
    cudaGetSymbolAddress((void**)&ret,  g_ret);
    cudaGetSymbolAddress((void**)&gate, g_gate);
    cudaGetSymbolAddress((void**)&wqh,  g_wqh);
    cudaGetSymbolAddress((void**)&woh,  g_woh);
    cudaGetSymbolAddress((void**)&whh,  g_whh);

    cudaFuncSetAttribute(mma_nt_h, cudaFuncAttributeMaxDynamicSharedMemorySize,
                         G_SMEM_BYTES);
    cudaFuncSetAttribute(mma_nt_64, cudaFuncAttributeMaxDynamicSharedMemorySize,
                         G64_SMEM_BYTES);

    {
        long long total = (long long)S1 + S2 + S3;
        int blocks = (int)(total / 1024);
        tohalf_all<<<blocks, 256>>>(Wqkv, Wo, headW, wqh, woh, whh);
    }

    embed_ln_kernel<<<NROW, 256>>>(ids, embedW, ln1_g, ln1_b, x, h);
    {
        int n = Ll*Hh*DK*DK;
        physics_kernel<<<(n + 255)/256, 256>>>(W_LTM, V_T0, V_gs, beta_tau, beta_gm,
                                               C_ch, gma, alpha, icth, ret, gate);
    }

    for (int l = 0; l < Ll; l++) {
        if (l > 0)
            ln_kernel<<<NROW, 256>>>(x, ln1_g + l*Dm, ln1_b + l*Dm, h);
        conv_kernel<<<NROW, 256>>>(h, conv_w + l*3*Dm, conv_b + l*Dm, h2h);

        dim3 gq((3*Dm)/128, NROW/128);
        mma_nt_h<<<gq, 128, G_SMEM_BYTES>>>(NROW, 3*Dm, Dm, h2h,
                                            wqh + (size_t)l*3*Dm*Dm, nullptr, qkv,
                                            lnk_g + l*DK, lnk_b + l*DK, 1);

        scan_kernel<<<Bb*Hh*4, 256>>>(qkv,
                                      ret  + (size_t)l*Hh*DK*DK,
                                      gate + (size_t)l*Hh*DK*DK,
                                      W_LTM + (size_t)l*Hh*DK*DK,
                                      yh);

        dim3 go(Dm/128, NROW/64);
        mma_nt_64<<<go, 128, G64_SMEM_BYTES>>>(NROW, Dm, Dm, yh,
                                               woh + (size_t)l*Dm*Dm, x, x);
    }

    lnh_kernel<<<NROW, 256>>>(x, lnf_g, lnf_b, hh);
    dim3 gh(Vv/128, NROW/128);
    mma_nt_h<<<gh, 128, G_SMEM_BYTES>>>(NROW, Vv, Dm, hh, whh, nullptr, out,
                                        nullptr, nullptr, 0);
}

// round 17
// speedup vs baseline: 1.0807x; 1.0047x over previous
#include <cuda_runtime.h>
#include <cuda_fp16.h>
#include <math.h>
#include <stdint.h>

// ---------------- problem constants ----------------
#define Dm    1024
#define Tlen  2048
#define Bb    4
#define Hh    16
#define DK    64
#define Ll    2
#define Vv    8192
#define NROW  (Bb*Tlen)          // 8192 token rows

// ---------------- scratch (device globals; no allocation allowed) ----------
__device__ float  g_x  [NROW*Dm];
__device__ float  g_h  [NROW*Dm];
__device__ __half g_h2h[NROW*Dm];
__device__ float  g_qkv[NROW*3*Dm];
__device__ __half g_yh [NROW*Dm];
__device__ __half g_hh [NROW*Dm];
__device__ float  g_ret [Ll*Hh*DK*DK];
__device__ float  g_gate[Ll*Hh*DK*DK];
__device__ __half g_wqh[Ll*3*Dm*Dm];
__device__ __half g_woh[Ll*Dm*Dm];
__device__ __half g_whh[Vv*Dm];

// ---------------- merged fp32 -> fp16 weight conversion ----------------
#define S1 (Ll*3*Dm*Dm)
#define S2 (Ll*Dm*Dm)
#define S3 (Vv*Dm)
__global__ void __launch_bounds__(256) tohalf_all(const float* __restrict__ wq,
                                                  const float* __restrict__ wo,
                                                  const float* __restrict__ wh,
                                                  __half* __restrict__ dq,
                                                  __half* __restrict__ dol,
                                                  __half* __restrict__ dh) {
    long long i = (long long)(blockIdx.x * blockDim.x + threadIdx.x) * 4;
    const float* s; __half* d; long long off;
    if (i < S1)            { s = wq; d = dq;  off = i; }
    else if (i < S1 + S2)  { s = wo; d = dol; off = i - S1; }
    else                   { s = wh; d = dh;  off = i - S1 - S2; }
    float4 v = *(const float4*)(s + off);
    *(__half2*)(d + off)     = __floats2half2_rn(v.x, v.y);
    *(__half2*)(d + off + 2) = __floats2half2_rn(v.z, v.w);
}

// ---------------- block reduce helper (blockDim == 256) ----------------
__device__ __forceinline__ float blockReduceSum(float v, float* sh) {
    #pragma unroll
    for (int o = 16; o; o >>= 1) v += __shfl_xor_sync(0xffffffffu, v, o);
    if ((threadIdx.x & 31) == 0) sh[threadIdx.x >> 5] = v;
    __syncthreads();
    float tot = 0.f;
    #pragma unroll
    for (int i = 0; i < 8; i++) tot += sh[i];
    __syncthreads();
    return tot;
}

// ---------------- fused embedding gather + layer-0 LN ----------------
__global__ void __launch_bounds__(256) embed_ln_kernel(const int* __restrict__ ids,
                                                       const float* __restrict__ W,
                                                       const float* __restrict__ g,
                                                       const float* __restrict__ b,
                                                       float* __restrict__ x,
                                                       float* __restrict__ h) {
    __shared__ float sh[8];
    int row = blockIdx.x;
    int id  = ids[row];
    const float* xr = W + (size_t)id * Dm;
    int i0 = threadIdx.x * 4;
    float4 xv = *(const float4*)(xr + i0);
    *(float4*)(x + (size_t)row * Dm + i0) = xv;
    float s = xv.x + xv.y + xv.z + xv.w;
    float mean = blockReduceSum(s, sh) * (1.f / Dm);
    float d0 = xv.x - mean, d1 = xv.y - mean, d2 = xv.z - mean, d3 = xv.w - mean;
    float sq = d0*d0 + d1*d1 + d2*d2 + d3*d3;
    float var = blockReduceSum(sq, sh) * (1.f / Dm);
    float rstd = rsqrtf(var + 1e-5f);
    float4 gv = *(const float4*)(g + i0);
    float4 bv = *(const float4*)(b + i0);
    float4 ov;
    ov.x = d0 * rstd * gv.x + bv.x;
    ov.y = d1 * rstd * gv.y + bv.y;
    ov.z = d2 * rstd * gv.z + bv.z;
    ov.w = d3 * rstd * gv.w + bv.w;
    *(float4*)(h + (size_t)row * Dm + i0) = ov;
}

// ---------------- layernorm (fp32 out) ----------------
__global__ void __launch_bounds__(256) ln_kernel(const float* __restrict__ x,
                                                 const float* __restrict__ g,
                                                 const float* __restrict__ b,
                                                 float* __restrict__ out) {
    __shared__ float sh[8];
    int row = blockIdx.x;
    const float* xr = x + (size_t)row * Dm;
    int i0 = threadIdx.x * 4;
    float4 xv = *(const float4*)(xr + i0);
    float s = xv.x + xv.y + xv.z + xv.w;
    float mean = blockReduceSum(s, sh) * (1.f / Dm);
    float d0 = xv.x - mean, d1 = xv.y - mean, d2 = xv.z - mean, d3 = xv.w - mean;
    float sq = d0*d0 + d1*d1 + d2*d2 + d3*d3;
    float var = blockReduceSum(sq, sh) * (1.f / Dm);
    float rstd = rsqrtf(var + 1e-5f);
    float4 gv = *(const float4*)(g + i0);
    float4 bv = *(const float4*)(b + i0);
    float4 ov;
    ov.x = d0 * rstd * gv.x + bv.x;
    ov.y = d1 * rstd * gv.y + bv.y;
    ov.z = d2 * rstd * gv.z + bv.z;
    ov.w = d3 * rstd * gv.w + bv.w;
    *(float4*)(out + (size_t)row * Dm + i0) = ov;
}

// ---------------- layernorm (half out, for head GEMM A) ----------------
__global__ void __launch_bounds__(256) lnh_kernel(const float* __restrict__ x,
                                                  const float* __restrict__ g,
                                                  const float* __restrict__ b,
                                                  __half* __restrict__ out) {
    __shared__ float sh[8];
    int row = blockIdx.x;
    const float* xr = x + (size_t)row * Dm;
    int i0 = threadIdx.x * 4;
    float4 xv = *(const float4*)(xr + i0);
    float s = xv.x + xv.y + xv.z + xv.w;
    float mean = blockReduceSum(s, sh) * (1.f / Dm);
    float d0 = xv.x - mean, d1 = xv.y - mean, d2 = xv.z - mean, d3 = xv.w - mean;
    float sq = d0*d0 + d1*d1 + d2*d2 + d3*d3;
    float var = blockReduceSum(sq, sh) * (1.f / Dm);
    float rstd = rsqrtf(var + 1e-5f);
    float4 gv = *(const float4*)(g + i0);
    float4 bv = *(const float4*)(b + i0);
    *(__half2*)(out + (size_t)row * Dm + i0) =
        __floats2half2_rn(d0 * rstd * gv.x + bv.x, d1 * rstd * gv.y + bv.y);
    *(__half2*)(out + (size_t)row * Dm + i0 + 2) =
        __floats2half2_rn(d2 * rstd * gv.z + bv.z, d3 * rstd * gv.w + bv.w);
}

// ---------------- causal depthwise conv (half out) ----------------
__global__ void __launch_bounds__(256) conv_kernel(const float* __restrict__ h,
                                                   const float* __restrict__ cw,
                                                   const float* __restrict__ cb,
                                                   __half* __restrict__ out) {
    int row = blockIdx.x;
    int t = row % Tlen;
    const float* h0 = h + (size_t)row * Dm;
    int i = threadIdx.x * 4;
    float4 cur = *(const float4*)(h0 + i);
    float4 w0 = *(const float4*)(cw + 0*Dm + i);
    float4 w1 = *(const float4*)(cw + 1*Dm + i);
    float4 w2 = *(const float4*)(cw + 2*Dm + i);
    float4 bb = *(const float4*)(cb + i);
    float4 z = make_float4(0.f, 0.f, 0.f, 0.f);
    float4 p1 = (t >= 1) ? *(const float4*)(h0 - Dm + i) : z;
    float4 p2 = (t >= 2) ? *(const float4*)(h0 - 2*Dm + i) : z;
    float ox = cur.x + w0.x*p2.x + w1.x*p1.x + w2.x*cur.x + bb.x;
    float oy = cur.y + w0.y*p2.y + w1.y*p1.y + w2.y*cur.y + bb.y;
    float oz = cur.z + w0.z*p2.z + w1.z*p1.z + w2.z*cur.z + bb.z;
    float ow = cur.w + w0.w*p2.w + w1.w*p1.w + w2.w*cur.w + bb.w;
    *(__half2*)(out + (size_t)row * Dm + i)     = __floats2half2_rn(ox, oy);
    *(__half2*)(out + (size_t)row * Dm + i + 2) = __floats2half2_rn(oz, ow);
}

// ---------------- static physics ----------------
__global__ void physics_kernel(const float* __restrict__ W_LTM,
                               const float* __restrict__ V_T0,
                               const float* __restrict__ V_gs,
                               const float* __restrict__ beta_tau,
                               const float* __restrict__ beta_gm,
                               const float* __restrict__ C_ch,
                               const float* __restrict__ gma,
                               const float* __restrict__ alpha,
                               const float* __restrict__ icth,
                               float* __restrict__ ret,
                               float* __restrict__ gate) {
    int idx = blockIdx.x * blockDim.x + threadIdx.x;
    if (idx >= Ll*Hh*DK*DK) return;
    int lh = idx / (DK*DK);
    int l  = lh / Hh;
    float veff = (V_gs[lh] - V_T0[lh]) + W_LTM[idx];
    float sp   = (veff > 20.f) ? veff : log1pf(expf(veff));
    float g_ch = beta_tau[lh] * sp;
    float r    = expf(-g_ch / C_ch[lh]);
    float G    = beta_gm[lh] * sp * (1.f / (1.f + expf(-veff)));
    float sgn  = tanhf(alpha[l] * (g_ch - icth[l]));
    ret[idx]  = r;
    gate[idx] = gma[lh] * sgn * G;
}

// ---------------- scan v5: v2 geometry + folded-W state (4 ops/elem) ------
// Ftilde = W + F;  Ftilde' = r*Ftilde + c + g*(vt*k), c = w*(1-r);  y = Ftilde.q
__global__ void __launch_bounds__(256) scan_kernel(const float* __restrict__ qkv,
                                                   const float* __restrict__ ret,
                                                   const float* __restrict__ gate,
                                                   const float* __restrict__ W,
                                                   __half* __restrict__ y) {
    int bh = blockIdx.x >> 2;
    int vq = blockIdx.x & 3;
    int b = bh / Hh, h = bh % Hh;
    int tid = threadIdx.x;
    int v = vq * 16 + (tid >> 4), part = tid & 15, koff = part * 4;

    float r[4], g[4], c[4], F[4];
    {
        int base = (h*DK + v)*DK + koff;
        #pragma unroll
        for (int j = 0; j < 4; j++) {
            r[j] = ret[base + j];
            g[j] = gate[base + j];
            float w = W[base + j];
            c[j] = w * (1.f - r[j]);
            F[j] = w;                 // Ftilde_0 = W (f=0)
        }
    }

    __shared__ float sbuf[2][16][192];
    bool loader = tid < 192;
    int which = tid >> 6, lane = tid & 63;
    size_t rowbase = (size_t)b * Tlen * (3*Dm) + h * DK;
    const float* src = qkv + rowbase + which * Dm + lane;
    float pre[16];
    if (loader) {
        #pragma unroll
        for (int j = 0; j < 16; j++) pre[j] = src[(size_t)j * (3*Dm)];
    }
    __half* yout = y + (size_t)b * Tlen * Dm + h * DK + v;

    const int NB = Tlen / 16;
    for (int tb = 0; tb < NB; tb++) {
        int p = tb & 1;
        if (loader) {
            #pragma unroll
            for (int j = 0; j < 16; j++) sbuf[p][j][tid] = pre[j];
        }
        __syncthreads();
        if (loader && tb + 1 < NB) {
            size_t tn = (size_t)(tb * 16 + 16);
            #pragma unroll
            for (int j = 0; j < 16; j++)
                pre[j] = src[(tn + j) * (3*Dm)];
        }
        #pragma unroll
        for (int st = 0; st < 16; st++) {
            float vt = sbuf[p][st][128 + v];
            float4 kk = *(const float4*)&sbuf[p][st][64 + koff];
            float4 qq = *(const float4*)&sbuf[p][st][koff];
            float t0 = fmaf(g[0], vt * kk.x, c[0]);
            float t1 = fmaf(g[1], vt * kk.y, c[1]);
            float t2 = fmaf(g[2], vt * kk.z, c[2]);
            float t3 = fmaf(g[3], vt * kk.w, c[3]);
            F[0] = fmaf(r[0], F[0], t0);
            F[1] = fmaf(r[1], F[1], t1);
            F[2] = fmaf(r[2], F[2], t2);
            F[3] = fmaf(r[3], F[3], t3);
            float yacc;
            yacc = F[0] * qq.x;
            yacc = fmaf(F[1], qq.y, yacc);
            yacc = fmaf(F[2], qq.z, yacc);
            yacc = fmaf(F[3], qq.w, yacc);
            yacc += __shfl_xor_sync(0xffffffffu, yacc, 1);
            yacc += __shfl_xor_sync(0xffffffffu, yacc, 2);
            yacc += __shfl_xor_sync(0xffffffffu, yacc, 4);
            yacc += __shfl_xor_sync(0xffffffffu, yacc, 8);
            if (part == 0) yout[(size_t)(tb * 16 + st) * Dm] = __float2half_rn(yacc);
        }
    }
}

// ======== shared GEMM building blocks ========
#define SUBT_B  8192
#define SS_B    (2*SUBT_B)
#define NSS     2
#define G_SMEM_BYTES (2*NSS*SS_B)          // 65536

__device__ __forceinline__ void cpasync16(uint32_t dst_smem, const void* src) {
    asm volatile("cp.async.cg.shared.global [%0], [%1], 16;"
                 :: "r"(dst_smem), "l"(src) : "memory");
}
__device__ __forceinline__ uint32_t smem_u32(const void* p) {
    uint32_t a;
    asm("{ .reg .u64 t; cvta.to.shared.u64 t, %1; cvt.u32.u64 %0, t; }"
        : "=r"(a) : "l"(p));
    return a;
}
__device__ __forceinline__ void ldm_x4(uint32_t& r0, uint32_t& r1,
                                       uint32_t& r2, uint32_t& r3, uint32_t addr) {
    asm volatile("ldmatrix.sync.aligned.m8n8.x4.shared.b16 {%0,%1,%2,%3}, [%4];"
                 : "=r"(r0), "=r"(r1), "=r"(r2), "=r"(r3) : "r"(addr));
}
__device__ __forceinline__ void mma_f16(float c[4],
                                        uint32_t a0, uint32_t a1, uint32_t a2, uint32_t a3,
                                        uint32_t b0, uint32_t b1) {
    asm volatile(
        "mma.sync.aligned.m16n8k16.row.col.f32.f16.f16.f32 "
        "{%0,%1,%2,%3}, {%4,%5,%6,%7}, {%8,%9}, {%0,%1,%2,%3};\n"
        : "+f"(c[0]), "+f"(c[1]), "+f"(c[2]), "+f"(c[3])
        : "r"(a0), "r"(a1), "r"(a2), "r"(a3), "r"(b0), "r"(b1));
}

__device__ __forceinline__ void issue_tile128(uint32_t base,
                                              const __half* __restrict__ Gp,
                                              int K, int k0, int tid) {
    #pragma unroll
    for (int hi = 0; hi < 4; hi++) {
        int c = tid + hi * 128;
        int mr = c >> 3, kk = c & 7;
        int m = mr * 2 + (kk >> 2);
        int h0 = (kk & 3) * 8;
        uint32_t dst = base + (uint32_t)(mr * 128 + ((kk ^ (mr & 7)) << 4));
        cpasync16(dst, Gp + (size_t)m * K + k0 + h0);
    }
}
__device__ __forceinline__ void issue_tile64(uint32_t base,
                                             const __half* __restrict__ Gp,
                                             int K, int k0, int tid) {
    #pragma unroll
    for (int hi = 0; hi < 2; hi++) {
        int c = tid + hi * 128;
        int mr = c >> 3, kk = c & 7;
        int m = mr * 2 + (kk >> 2);
        int h0 = (kk & 3) * 8;
        uint32_t dst = base + (uint32_t)(mr * 128 + ((kk ^ (mr & 7)) << 4));
        cpasync16(dst, Gp + (size_t)m * K + k0 + h0);
    }
}

__device__ __forceinline__ void issue_ss(uint32_t sbase, int ss,
                                         const __half* __restrict__ Agp,
                                         const __half* __restrict__ Bgp,
                                         int K, int k0, int tid) {
    uint32_t aB = sbase + (uint32_t)ss * SS_B;
    uint32_t bB = sbase + (uint32_t)(NSS * SS_B) + (uint32_t)ss * SS_B;
    issue_tile128(aB,          Agp, K, k0,      tid);
    issue_tile128(aB + SUBT_B, Agp, K, k0 + 32, tid);
    issue_tile128(bB,          Bgp, K, k0,      tid);
    issue_tile128(bB + SUBT_B, Bgp, K, k0 + 32, tid);
}

// ======== GEMM 128x128 (qkv + head), NSS=2, 3 CTA/SM, fused k-LN ========
__global__ void __launch_bounds__(128, 3) mma_nt_h(int M, int N, int K,
                                                   const __half* __restrict__ A,
                                                   const __half* __restrict__ B,
                                                   const float* __restrict__ Res,
                                                   float* __restrict__ C,
                                                   const float* __restrict__ lng,
                                                   const float* __restrict__ lnb,
                                                   int lnmode) {
    extern __shared__ __half smemh[];
    uint32_t sbase = smem_u32(smemh);
    int tid = threadIdx.x;
    int wid = tid >> 5, lane = tid & 31;
    int wm = (wid & 1) * 64;
    int wn = (wid >> 1) * 64;
    int m0 = blockIdx.y * 128, n0 = blockIdx.x * 128;
    int lg = lane >> 2;
    int lq = lane & 3;

    float acc[4][8][4];
    #pragma unroll
    for (int i = 0; i < 4; i++)
        #pragma unroll
        for (int j = 0; j < 8; j++)
            #pragma unroll
            for (int q = 0; q < 4; q++) acc[i][j][q] = 0.f;

    const __half* Agp = A + (size_t)m0 * K;
    const __half* Bgp = B + (size_t)n0 * K;

    int lm = lane & 15;
    int lc = lane >> 4;
    int mrA0 = (wm + lm) >> 1;
    int mrB0 = (wn + lm) >> 1;
    int halfbit = lm & 1;
    int kpA[2], kpB[2];
    #pragma unroll
    for (int kb = 0; kb < 2; kb++) {
        kpA[kb] = ((halfbit * 4 + kb * 2 + lc) ^ (mrA0 & 7)) << 4;
        kpB[kb] = ((halfbit * 4 + kb * 2 + lc) ^ (mrB0 & 7)) << 4;
    }
    uint32_t aRow = (uint32_t)(mrA0 * 128);
    uint32_t bRow = (uint32_t)(mrB0 * 128);

    int nSS = K >> 6;

    issue_ss(sbase, 0, Agp, Bgp, K, 0,  tid);
    asm volatile("cp.async.commit_group;");
    issue_ss(sbase, 1, Agp, Bgp, K, 64, tid);
    asm volatile("cp.async.commit_group;");

    for (int st = 0; st < nSS; st++) {
        int ss = st & 1;
        asm volatile("cp.async.wait_group 1;");
        __syncthreads();

        uint32_t aSS = sbase + (uint32_t)ss * SS_B + aRow;
        uint32_t bSS = sbase + (uint32_t)(NSS * SS_B) + (uint32_t)ss * SS_B + bRow;

        #pragma unroll
        for (int sub = 0; sub < 2; sub++) {
            uint32_t aBase = aSS + (uint32_t)(sub * SUBT_B);
            uint32_t bBase = bSS + (uint32_t)(sub * SUBT_B);
            #pragma unroll
            for (int kb = 0; kb < 2; kb++) {
                uint32_t af[4][4];
                #pragma unroll
                for (int i = 0; i < 4; i++)
                    ldm_x4(af[i][0], af[i][1], af[i][2], af[i][3],
                           aBase + (uint32_t)(i * 1024) + kpA[kb]);
                #pragma unroll
                for (int jj = 0; jj < 4; jj++) {
                    uint32_t b0, b1, b2, b3;
                    ldm_x4(b0, b1, b2, b3, bBase + (uint32_t)(jj * 1024) + kpB[kb]);
                    #pragma unroll
                    for (int i = 0; i < 4; i++) {
                        mma_f16(acc[i][jj*2],   af[i][0], af[i][1], af[i][2], af[i][3], b0, b2);
                        mma_f16(acc[i][jj*2+1], af[i][0], af[i][1], af[i][2], af[i][3], b1, b3);
                    }
                }
            }
        }
        __syncthreads();
        if (st + 2 < nSS)
            issue_ss(sbase, ss, Agp, Bgp, K, (st + 2) << 6, tid);
        asm volatile("cp.async.commit_group;");
    }

    bool do_ln = (lnmode != 0) && ((n0 + wn) >= Dm) && ((n0 + wn) < 2*Dm);
    #pragma unroll
    for (int i = 0; i < 4; i++) {
        int row = m0 + wm + i*16 + lg;
        float mA = 0.f, rA = 1.f, mB = 0.f, rB = 1.f;
        if (do_ln) {
            float s0 = 0.f, q0 = 0.f, s1 = 0.f, q1 = 0.f;
            #pragma unroll
            for (int j = 0; j < 8; j++) {
                s0 += acc[i][j][0] + acc[i][j][1];
                q0 += acc[i][j][0]*acc[i][j][0] + acc[i][j][1]*acc[i][j][1];
                s1 += acc[i][j][2] + acc[i][j][3];
                q1 += acc[i][j][2]*acc[i][j][2] + acc[i][j][3]*acc[i][j][3];
            }
            s0 += __shfl_xor_sync(0xffffffffu, s0, 1);
            s0 += __shfl_xor_sync(0xffffffffu, s0, 2);
            q0 += __shfl_xor_sync(0xffffffffu, q0, 1);
            q0 += __shfl_xor_sync(0xffffffffu, q0, 2);
            s1 += __shfl_xor_sync(0xffffffffu, s1, 1);
            s1 += __shfl_xor_sync(0xffffffffu, s1, 2);
            q1 += __shfl_xor_sync(0xffffffffu, q1, 1);
            q1 += __shfl_xor_sync(0xffffffffu, q1, 2);
            mA = s0 * (1.f/64);
            rA = rsqrtf(fmaxf(q0 * (1.f/64) - mA*mA, 0.f) + 1e-5f);
            mB = s1 * (1.f/64);
            rB = rsqrtf(fmaxf(q1 * (1.f/64) - mB*mB, 0.f) + 1e-5f);
        }
        #pragma unroll
        for (int j = 0; j < 8; j++) {
            int col = n0 + wn + j*8 + 2*lq;
            size_t o0 = (size_t)row * N + col;
            size_t o1 = (size_t)(row + 8) * N + col;
            float2 v0 = make_float2(acc[i][j][0], acc[i][j][1]);
            float2 v1 = make_float2(acc[i][j][2], acc[i][j][3]);
            if (do_ln) {
                int c = j*8 + 2*lq;
                float g0 = lng[c], b0 = lnb[c];
                float g1 = lng[c+1], b1 = lnb[c+1];
                v0.x = (v0.x - mA)*rA*g0 + b0;  v0.y = (v0.y - mA)*rA*g1 + b1;
                v1.x = (v1.x - mB)*rB*g0 + b0;  v1.y = (v1.y - mB)*rB*g1 + b1;
            }
            if (Res) {
                float2 q0 = *(const float2*)(Res + o0);
                float2 q1 = *(const float2*)(Res + o1);
                v0.x += q0.x; v0.y += q0.y;
                v1.x += q1.x; v1.y += q1.y;
            }
            *(float2*)(C + o0) = v0;
            *(float2*)(C + o1) = v1;
        }
    }
}

// ======== GEMM 64x128 CTA variant (Wo GEMM: better wave balance) ========
#define SUBT_A64  4096
#define SSA_B     (2*SUBT_A64)
#define SSB_B     (2*SUBT_B)
#define G64_SMEM_BYTES (NSS*(SSA_B + SSB_B))  // 49152

__device__ __forceinline__ void issue_ss64(uint32_t sbase, int ss,
                                           const __half* __restrict__ Agp,
                                           const __half* __restrict__ Bgp,
                                           int K, int k0, int tid) {
    uint32_t aB = sbase + (uint32_t)ss * SSA_B;
    uint32_t bB = sbase + (uint32_t)(NSS * SSA_B) + (uint32_t)ss * SSB_B;
    issue_tile64(aB,            Agp, K, k0,      tid);
    issue_tile64(aB + SUBT_A64, Agp, K, k0 + 32, tid);
    issue_tile128(bB,           Bgp, K, k0,      tid);
    issue_tile128(bB + SUBT_B,  Bgp, K, k0 + 32, tid);
}

__global__ void __launch_bounds__(128, 4) mma_nt_64(int M, int N, int K,
                                                    const __half* __restrict__ A,
                                                    const __half* __restrict__ B,
                                                    const float* __restrict__ Res,
                                                    float* __restrict__ C) {
    extern __shared__ __half smemh[];
    uint32_t sbase = smem_u32(smemh);
    int tid = threadIdx.x;
    int wid = tid >> 5, lane = tid & 31;
    int wn = wid * 32;
    int m0 = blockIdx.y * 64, n0 = blockIdx.x * 128;
    int lg = lane >> 2;
    int lq = lane & 3;

    float acc[4][4][4];
    #pragma unroll
    for (int i = 0; i < 4; i++)
        #pragma unroll
        for (int j = 0; j < 4; j++)
            #pragma unroll
            for (int q = 0; q < 4; q++) acc[i][j][q] = 0.f;

    const __half* Agp = A + (size_t)m0 * K;
    const __half* Bgp = B + (size_t)n0 * K;

    int lm = lane & 15;
    int lc = lane >> 4;
    int mrA0 = lm >> 1;
    int mrB0 = (wn + lm) >> 1;
    int halfbit = lm & 1;
    int kpA[2], kpB[2];
    #pragma unroll
    for (int kb = 0; kb < 2; kb++) {
        kpA[kb] = ((halfbit * 4 + kb * 2 + lc) ^ (mrA0 & 7)) << 4;
        kpB[kb] = ((halfbit * 4 + kb * 2 + lc) ^ (mrB0 & 7)) << 4;
    }
    uint32_t aRow = (uint32_t)(mrA0 * 128);
    uint32_t bRow = (uint32_t)(mrB0 * 128);

    int nSS = K >> 6;

    issue_ss64(sbase, 0, Agp, Bgp, K, 0,  tid);
    asm volatile("cp.async.commit_group;");
    issue_ss64(sbase, 1, Agp, Bgp, K, 64, tid);
    asm volatile("cp.async.commit_group;");

    for (int st = 0; st < nSS; st++) {
        int ss = st & 1;
        asm volatile("cp.async.wait_group 1;");
        __syncthreads();

        uint32_t aSS = sbase + (uint32_t)ss * SSA_B + aRow;
        uint32_t bSS = sbase + (uint32_t)(NSS * SSA_B) + (uint32_t)ss * SSB_B + bRow;

        #pragma unroll
        for (int sub = 0; sub < 2; sub++) {
            uint32_t aBase = aSS + (uint32_t)(sub * SUBT_A64);
            uint32_t bBase = bSS + (uint32_t)(sub * SUBT_B);
            #pragma unroll
            for (int kb = 0; kb < 2; kb++) {
                uint32_t af[4][4];
                #pragma unroll
                for (int i = 0; i < 4; i++)
                    ldm_x4(af[i][0], af[i][1], af[i][2], af[i][3],
                           aBase + (uint32_t)(i * 1024) + kpA[kb]);
                #pragma unroll
                for (int jj = 0; jj < 2; jj++) {
                    uint32_t b0, b1, b2, b3;
                    ldm_x4(b0, b1, b2, b3, bBase + (uint32_t)(jj * 1024) + kpB[kb]);
                    #pragma unroll
                    for (int i = 0; i < 4; i++) {
                        mma_f16(acc[i][jj*2],   af[i][0], af[i][1], af[i][2], af[i][3], b0, b2);
                        mma_f16(acc[i][jj*2+1], af[i][0], af[i][1], af[i][2], af[i][3], b1, b3);
                    }
                }
            }
        }
        __syncthreads();
        if (st + 2 < nSS)
            issue_ss64(sbase, ss, Agp, Bgp, K, (st + 2) << 6, tid);
        asm volatile("cp.async.commit_group;");
    }

    #pragma unroll
    for (int i = 0; i < 4; i++) {
        int row = m0 + i*16 + lg;
        #pragma unroll
        for (int j = 0; j < 4; j++) {
            int col = n0 + wn + j*8 + 2*lq;
            size_t o0 = (size_t)row * N + col;
            size_t o1 = (size_t)(row + 8) * N + col;
            float2 v0 = make_float2(acc[i][j][0], acc[i][j][1]);
            float2 v1 = make_float2(acc[i][j][2], acc[i][j][3]);
            if (Res) {
                float2 q0 = *(const float2*)(Res + o0);
                float2 q1 = *(const float2*)(Res + o1);
                v0.x += q0.x; v0.y += q0.y;
                v1.x += q1.x; v1.y += q1.y;
            }
            *(float2*)(C + o0) = v0;
            *(float2*)(C + o1) = v1;
        }
    }
}

// ---------------- launch ----------------
extern "C" void kernel_launch(void* const* d_in, const int* in_sizes, int n_in,
                              void* d_out, int out_size) {
    const int*   ids      = (const int*)  d_in[0];
    const float* embedW   = (const float*)d_in[2];
    const float* conv_w   = (const float*)d_in[3];
    const float* conv_b   = (const float*)d_in[4];
    const float* Wqkv     = (const float*)d_in[5];
    const float* Wo       = (const float*)d_in[6];
    const float* W_LTM    = (const float*)d_in[7];
    const float* V_T0     = (const float*)d_in[8];
    const float* V_gs     = (const float*)d_in[9];
    const float* beta_tau = (const float*)d_in[10];
    const float* beta_gm  = (const float*)d_in[11];
    const float* C_ch     = (const float*)d_in[12];
    const float* gma      = (const float*)d_in[13];
    const float* alpha    = (const float*)d_in[14];
    const float* icth     = (const float*)d_in[15];
    const float* ln1_g    = (const float*)d_in[16];
    const float* ln1_b    = (const float*)d_in[17];
    const float* lnk_g    = (const float*)d_in[18];
    const float* lnk_b    = (const float*)d_in[19];
    const float* lnf_g    = (const float*)d_in[20];
    const float* lnf_b    = (const float*)d_in[21];
    const float* headW    = (const float*)d_in[22];
    float* out = (float*)d_out;

    float *x, *h, *qkv, *ret, *gate;
    __half *h2h, *yh, *hh, *wqh, *woh, *whh;
    cudaGetSymbolAddress((void**)&x,    g_x);
    cudaGetSymbolAddress((void**)&h,    g_h);
    cudaGetSymbolAddress((void**)&h2h,  g_h2h);
    cudaGetSymbolAddress((void**)&qkv,  g_qkv);
    cudaGetSymbolAddress((void**)&yh,   g_yh);
    cudaGetSymbolAddress((void**)&hh,   g_hh);
    cudaGetSymbolAddress((void**)&ret,  g_ret);
    cudaGetSymbolAddress((void**)&gate, g_gate);
    cudaGetSymbolAddress((void**)&wqh,  g_wqh);
    cudaGetSymbolAddress((void**)&woh,  g_woh);
    cudaGetSymbolAddress((void**)&whh,  g_whh);

    cudaFuncSetAttribute(mma_nt_h, cudaFuncAttributeMaxDynamicSharedMemorySize,
                         G_SMEM_BYTES);
    cudaFuncSetAttribute(mma_nt_64, cudaFuncAttributeMaxDynamicSharedMemorySize,
                         G64_SMEM_BYTES);

    {
        long long total = (long long)S1 + S2 + S3;
        int blocks = (int)(total / 1024);
        tohalf_all<<<blocks, 256>>>(Wqkv, Wo, headW, wqh, woh, whh);
    }

    embed_ln_kernel<<<NROW, 256>>>(ids, embedW, ln1_g, ln1_b, x, h);
    {
        int n = Ll*Hh*DK*DK;
        physics_kernel<<<(n + 255)/256, 256>>>(W_LTM, V_T0, V_gs, beta_tau, beta_gm,
                                               C_ch, gma, alpha, icth, ret, gate);
    }

    for (int l = 0; l < Ll; l++) {
        if (l > 0)
            ln_kernel<<<NROW, 256>>>(x, ln1_g + l*Dm, ln1_b + l*Dm, h);
        conv_kernel<<<NROW, 256>>>(h, conv_w + l*3*Dm, conv_b + l*Dm, h2h);

        dim3 gq((3*Dm)/128, NROW/128);
        mma_nt_h<<<gq, 128, G_SMEM_BYTES>>>(NROW, 3*Dm, Dm, h2h,
                                            wqh + (size_t)l*3*Dm*Dm, nullptr, qkv,
                                            lnk_g + l*DK, lnk_b + l*DK, 1);

        scan_kernel<<<Bb*Hh*4, 256>>>(qkv,
                                      ret  + (size_t)l*Hh*DK*DK,
                                      gate + (size_t)l*Hh*DK*DK,
                                      W_LTM + (size_t)l*Hh*DK*DK,
                                      yh);

        dim3 go(Dm/128, NROW/64);
        mma_nt_64<<<go, 128, G64_SMEM_BYTES>>>(NROW, Dm, Dm, yh,
                                               woh + (size_t)l*Dm*Dm, x, x);
    }

    lnh_kernel<<<NROW, 256>>>(x, lnf_g, lnf_b, hh);
    dim3 gh(Vv/128, NROW/128);
    mma_nt_h<<<gh, 128, G_SMEM_BYTES>>>(NROW, Vv, Dm, hh, whh, nullptr, out,
                                        nullptr, nullptr, 0);
}